// round 11
// baseline (speedup 1.0000x reference)
#include <cuda_runtime.h>
#include <cuda_bf16.h>
#include <math.h>
#include <cstdint>

// Problem constants
static constexpr int Bn = 8;
static constexpr int Cn = 128;
static constexpr int On = 256;
static constexpr int Hn = 96;
static constexpr int Wn = 96;
static constexpr int HWn = Hn * Wn;        // 9216
static constexpr int KKn = 9;
static constexpr int CKn = Cn * KKn;       // 1152
static constexpr int NCH = 27;
static constexpr int KP  = 2 * CKn;        // 2304: A stored as [Ah | Al]
static constexpr int KP3 = 3 * CKn;        // 3456: logical GEMM K
static constexpr int MTOT = Bn * HWn;      // 73728
static constexpr int BM = 128, BN = 128, BK = 64;
static constexpr int NST = KP3 / BK;       // 54

// Scratch
__device__ float         g_offmask[Bn * NCH * HWn];
__device__ __nv_bfloat16 g_A2[(size_t)MTOT * KP];     // [Ah | Al] per row
__device__ __nv_bfloat16 g_B2[(size_t)On * KP3];      // [Bh | Bh | Bl] per row

// ---------------------------------------------------------------------------
// PTX helpers
// ---------------------------------------------------------------------------
__device__ __forceinline__ uint32_t smem_u32(const void* p) {
    uint32_t a;
    asm("{ .reg .u64 t; cvta.to.shared.u64 t, %1; cvt.u32.u64 %0, t; }"
        : "=r"(a) : "l"(p));
    return a;
}
__device__ __forceinline__ void cp_async16(uint32_t dst, const void* src) {
    asm volatile("cp.async.cg.shared.global [%0], [%1], 16;"
                 :: "r"(dst), "l"(src) : "memory");
}
#define CP_COMMIT() asm volatile("cp.async.commit_group;" ::: "memory")
#define CP_WAIT1()  asm volatile("cp.async.wait_group 1;" ::: "memory")

__device__ __forceinline__ void ldmx4(uint32_t& r0, uint32_t& r1,
                                      uint32_t& r2, uint32_t& r3, uint32_t addr) {
    asm volatile("ldmatrix.sync.aligned.m8n8.x4.shared.b16 {%0,%1,%2,%3}, [%4];"
                 : "=r"(r0), "=r"(r1), "=r"(r2), "=r"(r3) : "r"(addr));
}
__device__ __forceinline__ void mma_bf16(float* c, const uint32_t* a,
                                         uint32_t b0, uint32_t b1) {
    asm volatile(
        "mma.sync.aligned.m16n8k16.row.col.f32.bf16.bf16.f32 "
        "{%0,%1,%2,%3}, {%4,%5,%6,%7}, {%8,%9}, {%0,%1,%2,%3};"
        : "+f"(c[0]), "+f"(c[1]), "+f"(c[2]), "+f"(c[3])
        : "r"(a[0]), "r"(a[1]), "r"(a[2]), "r"(a[3]), "r"(b0), "r"(b1));
}

// ---------------------------------------------------------------------------
// Kernel: weight -> bf16 3-term layout [Bh | Bh | Bl], [O][KP3]
// ---------------------------------------------------------------------------
__global__ void prep_w(const float* __restrict__ w) {
    int i = blockIdx.x * 256 + threadIdx.x;
    if (i < On * CKn) {
        int o = i / CKn, ck = i % CKn;
        float v = w[i];
        __nv_bfloat16 hi = __float2bfloat16(v);
        __nv_bfloat16 lo = __float2bfloat16(v - __bfloat162float(hi));
        __nv_bfloat16* row = g_B2 + (size_t)o * KP3;
        row[ck]           = hi;
        row[CKn + ck]     = hi;
        row[2 * CKn + ck] = lo;
    }
}

// ---------------------------------------------------------------------------
// Kernel: offset + mask 3x3 conv (27 channels), fp32 direct.
// 2 pixels/thread (batch b and b+4): one smem weight read feeds both.
// ---------------------------------------------------------------------------
static constexpr int WS1_FLOATS = NCH * Cn * 12;
static constexpr int WS1_BYTES  = WS1_FLOATS * 4;

__global__ void __launch_bounds__(256) offmask_kernel(
    const float* __restrict__ x,
    const float* __restrict__ off_w, const float* __restrict__ off_b,
    const float* __restrict__ msk_w, const float* __restrict__ msk_b)
{
    extern __shared__ float ws[];
    int tid = threadIdx.x;
    for (int i = tid; i < WS1_FLOATS; i += 256) {
        int tap = i % 12;
        int c   = (i / 12) % Cn;
        int ch  = i / (12 * Cn);
        float v = 0.0f;
        if (tap < 9)
            v = (ch < 18) ? off_w[(ch * Cn + c) * 9 + tap]
                          : msk_w[((ch - 18) * Cn + c) * 9 + tap];
        ws[i] = v;
    }
    __syncthreads();

    int g = blockIdx.x * 256 + tid;       // 0 .. MTOT/2-1
    int b   = g / HWn;                    // 0..3
    int pix = g % HWn;
    int oh  = pix / Wn;
    int owp = pix % Wn;

    int  offs[9];
    bool valt[9];
#pragma unroll
    for (int kh = 0; kh < 3; kh++)
#pragma unroll
        for (int kw = 0; kw < 3; kw++) {
            int y  = oh - 1 + kh;
            int xx = owp - 1 + kw;
            bool v = (y >= 0 && y < Hn && xx >= 0 && xx < Wn);
            valt[kh * 3 + kw] = v;
            offs[kh * 3 + kw] = v ? (y * Wn + xx) : 0;
        }

    float acc0[NCH], acc1[NCH];
#pragma unroll
    for (int ch = 0; ch < NCH; ch++) {
        float bv = (ch < 18) ? off_b[ch] : msk_b[ch - 18];
        acc0[ch] = bv;
        acc1[ch] = bv;
    }

    const float* xb0 = x + (size_t)b * Cn * HWn;
    const float* xb1 = xb0 + (size_t)4 * Cn * HWn;
    for (int c = 0; c < Cn; c++) {
        float xv0[9], xv1[9];
        const float* xc0 = xb0 + c * HWn;
        const float* xc1 = xb1 + c * HWn;
#pragma unroll
        for (int j = 0; j < 9; j++) {
            xv0[j] = valt[j] ? xc0[offs[j]] : 0.0f;
            xv1[j] = valt[j] ? xc1[offs[j]] : 0.0f;
        }
#pragma unroll
        for (int ch = 0; ch < NCH; ch++) {
            const float4* wp = (const float4*)&ws[(ch * Cn + c) * 12];
            float4 wa = wp[0];
            float4 wb = wp[1];
            float  w8 = ws[(ch * Cn + c) * 12 + 8];
            acc0[ch] += xv0[0] * wa.x + xv0[1] * wa.y + xv0[2] * wa.z + xv0[3] * wa.w
                      + xv0[4] * wb.x + xv0[5] * wb.y + xv0[6] * wb.z + xv0[7] * wb.w
                      + xv0[8] * w8;
            acc1[ch] += xv1[0] * wa.x + xv1[1] * wa.y + xv1[2] * wa.z + xv1[3] * wa.w
                      + xv1[4] * wb.x + xv1[5] * wb.y + xv1[6] * wb.z + xv1[7] * wb.w
                      + xv1[8] * w8;
        }
    }

    float* dst0 = g_offmask + (size_t)b * NCH * HWn + pix;
    float* dst1 = dst0 + (size_t)4 * NCH * HWn;
#pragma unroll
    for (int ch = 0; ch < NCH; ch++) {
        float v0 = acc0[ch], v1 = acc1[ch];
        if (ch >= 18) {
            v0 = 1.0f / (1.0f + expf(-v0));
            v1 = 1.0f / (1.0f + expf(-v1));
        }
        dst0[ch * HWn] = v0;
        dst1[ch * HWn] = v1;
    }
}

// ---------------------------------------------------------------------------
// Kernel: bilinear gather -> A2 [M][KP] bf16 [Ah | Al], mask folded in.
// v4: compute phase lane=pixel (coalesced x loads), store phase lane=ck
// (coalesced A2 stores), bridged by per-warp 32x33 uint32 smem transpose tile.
// ---------------------------------------------------------------------------
__global__ void __launch_bounds__(256) gather_kernel(const float* __restrict__ x)
{
    __shared__ float4   mw4[KKn * 32];          // [k][p]
    __shared__ int4     mo4[KKn * 32];          // [k][p]
    __shared__ uint32_t stg[8][32][33];         // per-warp [ck][px], packed hi|lo

    int blk = blockIdx.x;
    int b   = blk / (Hn * 3);
    int r   = blk % (Hn * 3);
    int oh  = r / 3;
    int ow0 = (r % 3) * 32;
    int tid  = threadIdx.x;
    int wid  = tid >> 5;
    int lane = tid & 31;

    const float* om = g_offmask + (size_t)b * NCH * HWn;
    for (int i = tid; i < KKn * 32; i += 256) {
        int k = i >> 5;
        int p = i & 31;
        int pix = oh * Wn + ow0 + p;
        float offy = om[(2 * k) * HWn + pix];
        float offx = om[(2 * k + 1) * HWn + pix];
        float m    = om[(18 + k) * HWn + pix];
        float py = (float)(oh - 1 + k / 3) + offy;
        float px = (float)(ow0 + p - 1 + k % 3) + offx;
        float y0f = floorf(py), x0f = floorf(px);
        int y0 = (int)y0f, x0 = (int)x0f;
        int y1 = y0 + 1,  x1 = x0 + 1;
        float wy1 = py - y0f, wy0 = 1.0f - wy1;
        float wx1 = px - x0f, wx0 = 1.0f - wx1;
        bool vy0 = (y0 >= 0 && y0 < Hn), vy1 = (y1 >= 0 && y1 < Hn);
        bool vx0 = (x0 >= 0 && x0 < Wn), vx1 = (x1 >= 0 && x1 < Wn);
        int cy0 = min(max(y0, 0), Hn - 1), cy1 = min(max(y1, 0), Hn - 1);
        int cx0 = min(max(x0, 0), Wn - 1), cx1 = min(max(x1, 0), Wn - 1);
        mw4[i] = make_float4(
            wy0 * wx0 * m * ((vy0 && vx0) ? 1.0f : 0.0f),
            wy0 * wx1 * m * ((vy0 && vx1) ? 1.0f : 0.0f),
            wy1 * wx0 * m * ((vy1 && vx0) ? 1.0f : 0.0f),
            wy1 * wx1 * m * ((vy1 && vx1) ? 1.0f : 0.0f));
        mo4[i] = make_int4(cy0 * Wn + cx0, cy0 * Wn + cx1,
                           cy1 * Wn + cx0, cy1 * Wn + cx1);
    }
    __syncthreads();

    const float* xb = x + (size_t)b * Cn * HWn;
    size_t arow0 = ((size_t)b * HWn + oh * Wn + ow0) * KP;

    // 36 sub-chunks of 32 consecutive ck, distributed over 8 warps
    for (int sc = wid; sc < 36; sc += 8) {
        int ck0 = sc * 32;
        // compute phase: iterate ck within chunk, lane = pixel
#pragma unroll 4
        for (int i = 0; i < 32; i++) {
            int ck = ck0 + i;
            int c = ck / 9, k = ck - c * 9;
            const float* xc = xb + c * HWn;
            float4 w = mw4[k * 32 + lane];
            int4   o = mo4[k * 32 + lane];
            float v = w.x * xc[o.x] + w.y * xc[o.y]
                    + w.z * xc[o.z] + w.w * xc[o.w];
            __nv_bfloat16 hi = __float2bfloat16(v);
            __nv_bfloat16 lo = __float2bfloat16(v - __bfloat162float(hi));
            stg[wid][i][lane] = ((uint32_t)__bfloat16_as_ushort(hi) << 16)
                              | (uint32_t)__bfloat16_as_ushort(lo);
        }
        __syncwarp();
        // store phase: lane = ck index -> coalesced 64B stores
#pragma unroll 4
        for (int p = 0; p < 32; p++) {
            uint32_t u = stg[wid][lane][p];
            __nv_bfloat16* dst = g_A2 + arow0 + (size_t)p * KP;
            dst[ck0 + lane]       = __ushort_as_bfloat16((unsigned short)(u >> 16));
            dst[CKn + ck0 + lane] = __ushort_as_bfloat16((unsigned short)(u & 0xFFFF));
        }
        __syncwarp();
    }
}

// ---------------------------------------------------------------------------
// Kernel: bf16 HMMA GEMM, CTA 128x128, BK=64, 3-stage cp.async pipeline.
// K'=3456 (3-term split, A segment 3 aliases 1). Pitch 144B.
// Grid (N=2, M=576): N-tiles of same M-row adjacent -> A L2 reuse.
// ---------------------------------------------------------------------------
static constexpr int PITCH  = 144;
static constexpr int ABYTES = BM * PITCH;         // 18432
static constexpr int BUFB   = 2 * ABYTES;         // 36864
static constexpr int GEMM_SMEM = 3 * BUFB;        // 110592

__global__ void __launch_bounds__(256, 2) gemm_kernel(
    const float* __restrict__ bias, float* __restrict__ out)
{
    extern __shared__ __align__(16) char sm[];
    uint32_t sb = smem_u32(sm);
    int tid  = threadIdx.x;
    int wid  = tid >> 5;
    int lane = tid & 31;
    int wm = wid & 3;
    int wn = wid >> 2;

    int row0 = blockIdx.y * BM;
    int col0 = blockIdx.x * BN;

    auto load_stage = [&](int s) {
        int kc  = s * BK;
        int akc = (kc < KP) ? kc : kc - KP;
        uint32_t dst = sb + (s % 3) * BUFB;
#pragma unroll
        for (int i = 0; i < 4; i++) {
            int ch = tid + i * 256;
            int r = ch >> 3, u = ch & 7;
            cp_async16(dst + r * PITCH + u * 16,
                       g_A2 + (size_t)(row0 + r) * KP + akc + u * 8);
        }
        uint32_t dstb = dst + ABYTES;
#pragma unroll
        for (int i = 0; i < 4; i++) {
            int ch = tid + i * 256;
            int r = ch >> 3, u = ch & 7;
            cp_async16(dstb + r * PITCH + u * 16,
                       g_B2 + (size_t)(col0 + r) * KP3 + kc + u * 8);
        }
        CP_COMMIT();
    };

    float acc[2][8][4];
#pragma unroll
    for (int mt = 0; mt < 2; mt++)
#pragma unroll
        for (int nt = 0; nt < 8; nt++)
#pragma unroll
            for (int e = 0; e < 4; e++) acc[mt][nt][e] = 0.0f;

    load_stage(0);
    load_stage(1);

    int lrow = lane & 15;
    int lcol = (lane >> 4) * 8;

    for (int s = 0; s < NST; s++) {
        CP_WAIT1();
        __syncthreads();
        if (s + 2 < NST) load_stage(s + 2);

        uint32_t bufA = sb + (s % 3) * BUFB;
        uint32_t bufB = bufA + ABYTES;

#pragma unroll
        for (int kk = 0; kk < 4; kk++) {
            int colb = (kk * 16 + lcol) * 2;
            uint32_t a[2][4];
#pragma unroll
            for (int mt = 0; mt < 2; mt++) {
                int row = wm * 32 + mt * 16 + lrow;
                ldmx4(a[mt][0], a[mt][1], a[mt][2], a[mt][3],
                      bufA + row * PITCH + colb);
            }
#pragma unroll
            for (int ntp = 0; ntp < 4; ntp++) {
                int row = wn * 64 + ntp * 16 + lrow;
                uint32_t b0, b1, b2, b3;
                ldmx4(b0, b1, b2, b3, bufB + row * PITCH + colb);
#pragma unroll
                for (int mt = 0; mt < 2; mt++) {
                    mma_bf16(acc[mt][2 * ntp],     a[mt], b0, b2);
                    mma_bf16(acc[mt][2 * ntp + 1], a[mt], b1, b3);
                }
            }
        }
    }

    // Epilogue (validated mapping)
    int quad = lane >> 2;
    int tq   = lane & 3;
#pragma unroll
    for (int mt = 0; mt < 2; mt++) {
        int m = row0 + wm * 32 + mt * 16 + quad;
        int b   = m / HWn;
        int pix = m % HWn;
        float* ob = out + (size_t)b * On * HWn;
#pragma unroll
        for (int nt = 0; nt < 8; nt++) {
            int o = col0 + wn * 64 + nt * 8 + tq * 2;
            float b0v = __ldg(bias + o);
            float b1v = __ldg(bias + o + 1);
            float* p0 = ob + (size_t)o * HWn + pix;
            float* p1 = ob + (size_t)(o + 1) * HWn + pix;
            p0[0] = acc[mt][nt][0] + b0v;
            p1[0] = acc[mt][nt][1] + b1v;
            p0[8] = acc[mt][nt][2] + b0v;
            p1[8] = acc[mt][nt][3] + b1v;
        }
    }
}

// ---------------------------------------------------------------------------
// Launch
// ---------------------------------------------------------------------------
extern "C" void kernel_launch(void* const* d_in, const int* in_sizes, int n_in,
                              void* d_out, int out_size)
{
    const float* x        = (const float*)d_in[0];
    const float* offset_w = (const float*)d_in[1];
    const float* offset_b = (const float*)d_in[2];
    const float* mask_w   = (const float*)d_in[3];
    const float* mask_b   = (const float*)d_in[4];
    const float* weight   = (const float*)d_in[5];
    const float* bias     = (const float*)d_in[6];
    float* out = (float*)d_out;

    cudaFuncSetAttribute(offmask_kernel,
                         cudaFuncAttributeMaxDynamicSharedMemorySize, WS1_BYTES);
    cudaFuncSetAttribute(gemm_kernel,
                         cudaFuncAttributeMaxDynamicSharedMemorySize, GEMM_SMEM);

    prep_w<<<(On * CKn + 255) / 256, 256>>>(weight);
    offmask_kernel<<<(Bn * HWn / 2) / 256, 256, WS1_BYTES>>>(
        x, offset_w, offset_b, mask_w, mask_b);
    gather_kernel<<<Bn * Hn * 3, 256>>>(x);
    dim3 grid(On / BN, MTOT / BM);
    gemm_kernel<<<grid, 256, GEMM_SMEM>>>(bias, out);
}

// round 12
// speedup vs baseline: 1.8217x; 1.8217x over previous
#include <cuda_runtime.h>
#include <cuda_bf16.h>
#include <math.h>
#include <cstdint>

// Problem constants
static constexpr int Bn = 8;
static constexpr int Cn = 128;
static constexpr int On = 256;
static constexpr int Hn = 96;
static constexpr int Wn = 96;
static constexpr int HWn = Hn * Wn;        // 9216
static constexpr int KKn = 9;
static constexpr int CKn = Cn * KKn;       // 1152
static constexpr int NCH = 27;
static constexpr int KP  = 2 * CKn;        // 2304: A stored as [Ah | Al]
static constexpr int KP3 = 3 * CKn;        // 3456: logical GEMM K
static constexpr int MTOT = Bn * HWn;      // 73728
static constexpr int BM = 128, BN = 128, BK = 64;
static constexpr int NST = KP3 / BK;       // 54

// Scratch
__device__ float         g_offmask[Bn * NCH * HWn];
__device__ float         g_xt[(size_t)Bn * HWn * Cn];  // x transposed to NHWC
__device__ __nv_bfloat16 g_A2[(size_t)MTOT * KP];      // [Ah | Al], K k-major
__device__ __nv_bfloat16 g_B2[(size_t)On * KP3];       // [Bh | Bh | Bl], k-major

// ---------------------------------------------------------------------------
// PTX helpers
// ---------------------------------------------------------------------------
__device__ __forceinline__ uint32_t smem_u32(const void* p) {
    uint32_t a;
    asm("{ .reg .u64 t; cvta.to.shared.u64 t, %1; cvt.u32.u64 %0, t; }"
        : "=r"(a) : "l"(p));
    return a;
}
__device__ __forceinline__ void cp_async16(uint32_t dst, const void* src) {
    asm volatile("cp.async.cg.shared.global [%0], [%1], 16;"
                 :: "r"(dst), "l"(src) : "memory");
}
#define CP_COMMIT() asm volatile("cp.async.commit_group;" ::: "memory")
#define CP_WAIT1()  asm volatile("cp.async.wait_group 1;" ::: "memory")

__device__ __forceinline__ void ldmx4(uint32_t& r0, uint32_t& r1,
                                      uint32_t& r2, uint32_t& r3, uint32_t addr) {
    asm volatile("ldmatrix.sync.aligned.m8n8.x4.shared.b16 {%0,%1,%2,%3}, [%4];"
                 : "=r"(r0), "=r"(r1), "=r"(r2), "=r"(r3) : "r"(addr));
}
__device__ __forceinline__ void mma_bf16(float* c, const uint32_t* a,
                                         uint32_t b0, uint32_t b1) {
    asm volatile(
        "mma.sync.aligned.m16n8k16.row.col.f32.bf16.bf16.f32 "
        "{%0,%1,%2,%3}, {%4,%5,%6,%7}, {%8,%9}, {%0,%1,%2,%3};"
        : "+f"(c[0]), "+f"(c[1]), "+f"(c[2]), "+f"(c[3])
        : "r"(a[0]), "r"(a[1]), "r"(a[2]), "r"(a[3]), "r"(b0), "r"(b1));
}

// ---------------------------------------------------------------------------
// Kernel: x NCHW -> NHWC (tiled 32x32 smem transpose)
// grid (HW/32, C/32, B), 256 threads
// ---------------------------------------------------------------------------
__global__ void __launch_bounds__(256) transpose_x(const float* __restrict__ x)
{
    __shared__ float t[32][33];
    int b  = blockIdx.z;
    int c0 = blockIdx.y * 32;
    int hw0 = blockIdx.x * 32;
    int tid = threadIdx.x;
    int lx = tid & 31, ly = tid >> 5;

    const float* xb = x + ((size_t)b * Cn + c0) * HWn + hw0;
#pragma unroll
    for (int i = 0; i < 4; i++) {
        int c = ly + i * 8;
        t[c][lx] = xb[(size_t)c * HWn + lx];
    }
    __syncthreads();
    float* xtb = g_xt + ((size_t)b * HWn + hw0) * Cn + c0;
#pragma unroll
    for (int i = 0; i < 4; i++) {
        int hw = ly + i * 8;
        xtb[(size_t)hw * Cn + lx] = t[lx][hw];
    }
}

// ---------------------------------------------------------------------------
// Kernel: weight -> bf16 3-term layout [Bh | Bh | Bl], K k-major (ck'=k*128+c)
// ---------------------------------------------------------------------------
__global__ void prep_w(const float* __restrict__ w) {
    int i = blockIdx.x * 256 + threadIdx.x;
    if (i < On * CKn) {
        int o = i / CKn, r = i % CKn;
        int c = r / 9, k = r % 9;
        int ckp = k * Cn + c;
        float v = w[i];
        __nv_bfloat16 hi = __float2bfloat16(v);
        __nv_bfloat16 lo = __float2bfloat16(v - __bfloat162float(hi));
        __nv_bfloat16* row = g_B2 + (size_t)o * KP3;
        row[ckp]           = hi;
        row[CKn + ckp]     = hi;
        row[2 * CKn + ckp] = lo;
    }
}

// ---------------------------------------------------------------------------
// Kernel: offset + mask 3x3 conv (27 channels), fp32 direct.
// 2 pixels/thread (batch b and b+4): one smem weight read feeds both.
// ---------------------------------------------------------------------------
static constexpr int WS1_FLOATS = NCH * Cn * 12;
static constexpr int WS1_BYTES  = WS1_FLOATS * 4;

__global__ void __launch_bounds__(256) offmask_kernel(
    const float* __restrict__ x,
    const float* __restrict__ off_w, const float* __restrict__ off_b,
    const float* __restrict__ msk_w, const float* __restrict__ msk_b)
{
    extern __shared__ float ws[];
    int tid = threadIdx.x;
    for (int i = tid; i < WS1_FLOATS; i += 256) {
        int tap = i % 12;
        int c   = (i / 12) % Cn;
        int ch  = i / (12 * Cn);
        float v = 0.0f;
        if (tap < 9)
            v = (ch < 18) ? off_w[(ch * Cn + c) * 9 + tap]
                          : msk_w[((ch - 18) * Cn + c) * 9 + tap];
        ws[i] = v;
    }
    __syncthreads();

    int g = blockIdx.x * 256 + tid;       // 0 .. MTOT/2-1
    int b   = g / HWn;                    // 0..3
    int pix = g % HWn;
    int oh  = pix / Wn;
    int owp = pix % Wn;

    int  offs[9];
    bool valt[9];
#pragma unroll
    for (int kh = 0; kh < 3; kh++)
#pragma unroll
        for (int kw = 0; kw < 3; kw++) {
            int y  = oh - 1 + kh;
            int xx = owp - 1 + kw;
            bool v = (y >= 0 && y < Hn && xx >= 0 && xx < Wn);
            valt[kh * 3 + kw] = v;
            offs[kh * 3 + kw] = v ? (y * Wn + xx) : 0;
        }

    float acc0[NCH], acc1[NCH];
#pragma unroll
    for (int ch = 0; ch < NCH; ch++) {
        float bv = (ch < 18) ? off_b[ch] : msk_b[ch - 18];
        acc0[ch] = bv;
        acc1[ch] = bv;
    }

    const float* xb0 = x + (size_t)b * Cn * HWn;
    const float* xb1 = xb0 + (size_t)4 * Cn * HWn;
    for (int c = 0; c < Cn; c++) {
        float xv0[9], xv1[9];
        const float* xc0 = xb0 + c * HWn;
        const float* xc1 = xb1 + c * HWn;
#pragma unroll
        for (int j = 0; j < 9; j++) {
            xv0[j] = valt[j] ? xc0[offs[j]] : 0.0f;
            xv1[j] = valt[j] ? xc1[offs[j]] : 0.0f;
        }
#pragma unroll
        for (int ch = 0; ch < NCH; ch++) {
            const float4* wp = (const float4*)&ws[(ch * Cn + c) * 12];
            float4 wa = wp[0];
            float4 wb = wp[1];
            float  w8 = ws[(ch * Cn + c) * 12 + 8];
            acc0[ch] += xv0[0] * wa.x + xv0[1] * wa.y + xv0[2] * wa.z + xv0[3] * wa.w
                      + xv0[4] * wb.x + xv0[5] * wb.y + xv0[6] * wb.z + xv0[7] * wb.w
                      + xv0[8] * w8;
            acc1[ch] += xv1[0] * wa.x + xv1[1] * wa.y + xv1[2] * wa.z + xv1[3] * wa.w
                      + xv1[4] * wb.x + xv1[5] * wb.y + xv1[6] * wb.z + xv1[7] * wb.w
                      + xv1[8] * w8;
        }
    }

    float* dst0 = g_offmask + (size_t)b * NCH * HWn + pix;
    float* dst1 = dst0 + (size_t)4 * NCH * HWn;
#pragma unroll
    for (int ch = 0; ch < NCH; ch++) {
        float v0 = acc0[ch], v1 = acc1[ch];
        if (ch >= 18) {
            v0 = 1.0f / (1.0f + expf(-v0));
            v1 = 1.0f / (1.0f + expf(-v1));
        }
        dst0[ch * HWn] = v0;
        dst1[ch * HWn] = v1;
    }
}

// ---------------------------------------------------------------------------
// Kernel: bilinear gather -> A2 [M][KP] bf16 [Ah | Al], K k-major.
// v5: NHWC x -> each (px,tap) corner is 128 consecutive floats (coalesced);
// output k-major -> 128 consecutive bf16 stores. Warp = one (px,tap) task.
// ---------------------------------------------------------------------------
__global__ void __launch_bounds__(256) gather_kernel()
{
    __shared__ float4 mw4[32 * KKn];     // [p*9+k]
    __shared__ int4   mo4[32 * KKn];

    int blk = blockIdx.x;
    int b   = blk / (Hn * 3);
    int r   = blk % (Hn * 3);
    int oh  = r / 3;
    int ow0 = (r % 3) * 32;
    int tid  = threadIdx.x;
    int wid  = tid >> 5;
    int lane = tid & 31;

    const float* om = g_offmask + (size_t)b * NCH * HWn;
    for (int i = tid; i < 32 * KKn; i += 256) {
        int p = i / KKn;
        int k = i % KKn;
        int pix = oh * Wn + ow0 + p;
        float offy = om[(2 * k) * HWn + pix];
        float offx = om[(2 * k + 1) * HWn + pix];
        float m    = om[(18 + k) * HWn + pix];
        float py = (float)(oh - 1 + k / 3) + offy;
        float px = (float)(ow0 + p - 1 + k % 3) + offx;
        float y0f = floorf(py), x0f = floorf(px);
        int y0 = (int)y0f, x0 = (int)x0f;
        int y1 = y0 + 1,  x1 = x0 + 1;
        float wy1 = py - y0f, wy0 = 1.0f - wy1;
        float wx1 = px - x0f, wx0 = 1.0f - wx1;
        bool vy0 = (y0 >= 0 && y0 < Hn), vy1 = (y1 >= 0 && y1 < Hn);
        bool vx0 = (x0 >= 0 && x0 < Wn), vx1 = (x1 >= 0 && x1 < Wn);
        int cy0 = min(max(y0, 0), Hn - 1), cy1 = min(max(y1, 0), Hn - 1);
        int cx0 = min(max(x0, 0), Wn - 1), cx1 = min(max(x1, 0), Wn - 1);
        mw4[i] = make_float4(
            wy0 * wx0 * m * ((vy0 && vx0) ? 1.0f : 0.0f),
            wy0 * wx1 * m * ((vy0 && vx1) ? 1.0f : 0.0f),
            wy1 * wx0 * m * ((vy1 && vx0) ? 1.0f : 0.0f),
            wy1 * wx1 * m * ((vy1 && vx1) ? 1.0f : 0.0f));
        mo4[i] = make_int4(cy0 * Wn + cx0, cy0 * Wn + cx1,
                           cy1 * Wn + cx0, cy1 * Wn + cx1);
    }
    __syncthreads();

    const float* xtb = g_xt + (size_t)b * HWn * Cn;
    size_t arow0 = ((size_t)b * HWn + oh * Wn + ow0) * KP;

    // 288 (p,k) tasks over 8 warps; lane strides channels (coalesced both ways)
    for (int i = wid; i < 32 * KKn; i += 8) {
        int p = i / KKn;
        int k = i % KKn;
        float4 w = mw4[i];
        int4   o = mo4[i];
        const float* c00 = xtb + (size_t)o.x * Cn;
        const float* c01 = xtb + (size_t)o.y * Cn;
        const float* c10 = xtb + (size_t)o.z * Cn;
        const float* c11 = xtb + (size_t)o.w * Cn;
        __nv_bfloat16* dst = g_A2 + arow0 + (size_t)p * KP + k * Cn;
#pragma unroll
        for (int it = 0; it < 4; it++) {
            int c = it * 32 + lane;
            float v = w.x * c00[c] + w.y * c01[c]
                    + w.z * c10[c] + w.w * c11[c];
            __nv_bfloat16 hi = __float2bfloat16(v);
            __nv_bfloat16 lo = __float2bfloat16(v - __bfloat162float(hi));
            dst[c]       = hi;
            dst[CKn + c] = lo;
        }
    }
}

// ---------------------------------------------------------------------------
// Kernel: bf16 HMMA GEMM, CTA 128x128, BK=64, 3-stage cp.async pipeline.
// K'=3456 (3-term split, A segment 3 aliases 1). Pitch 144B.
// Grid (N=2, M=576). UNCHANGED from the 397us measured version.
// ---------------------------------------------------------------------------
static constexpr int PITCH  = 144;
static constexpr int ABYTES = BM * PITCH;         // 18432
static constexpr int BUFB   = 2 * ABYTES;         // 36864
static constexpr int GEMM_SMEM = 3 * BUFB;        // 110592

__global__ void __launch_bounds__(256, 2) gemm_kernel(
    const float* __restrict__ bias, float* __restrict__ out)
{
    extern __shared__ __align__(16) char sm[];
    uint32_t sb = smem_u32(sm);
    int tid  = threadIdx.x;
    int wid  = tid >> 5;
    int lane = tid & 31;
    int wm = wid & 3;
    int wn = wid >> 2;

    int row0 = blockIdx.y * BM;
    int col0 = blockIdx.x * BN;

    auto load_stage = [&](int s) {
        int kc  = s * BK;
        int akc = (kc < KP) ? kc : kc - KP;
        uint32_t dst = sb + (s % 3) * BUFB;
#pragma unroll
        for (int i = 0; i < 4; i++) {
            int ch = tid + i * 256;
            int r = ch >> 3, u = ch & 7;
            cp_async16(dst + r * PITCH + u * 16,
                       g_A2 + (size_t)(row0 + r) * KP + akc + u * 8);
        }
        uint32_t dstb = dst + ABYTES;
#pragma unroll
        for (int i = 0; i < 4; i++) {
            int ch = tid + i * 256;
            int r = ch >> 3, u = ch & 7;
            cp_async16(dstb + r * PITCH + u * 16,
                       g_B2 + (size_t)(col0 + r) * KP3 + kc + u * 8);
        }
        CP_COMMIT();
    };

    float acc[2][8][4];
#pragma unroll
    for (int mt = 0; mt < 2; mt++)
#pragma unroll
        for (int nt = 0; nt < 8; nt++)
#pragma unroll
            for (int e = 0; e < 4; e++) acc[mt][nt][e] = 0.0f;

    load_stage(0);
    load_stage(1);

    int lrow = lane & 15;
    int lcol = (lane >> 4) * 8;

    for (int s = 0; s < NST; s++) {
        CP_WAIT1();
        __syncthreads();
        if (s + 2 < NST) load_stage(s + 2);

        uint32_t bufA = sb + (s % 3) * BUFB;
        uint32_t bufB = bufA + ABYTES;

#pragma unroll
        for (int kk = 0; kk < 4; kk++) {
            int colb = (kk * 16 + lcol) * 2;
            uint32_t a[2][4];
#pragma unroll
            for (int mt = 0; mt < 2; mt++) {
                int row = wm * 32 + mt * 16 + lrow;
                ldmx4(a[mt][0], a[mt][1], a[mt][2], a[mt][3],
                      bufA + row * PITCH + colb);
            }
#pragma unroll
            for (int ntp = 0; ntp < 4; ntp++) {
                int row = wn * 64 + ntp * 16 + lrow;
                uint32_t b0, b1, b2, b3;
                ldmx4(b0, b1, b2, b3, bufB + row * PITCH + colb);
#pragma unroll
                for (int mt = 0; mt < 2; mt++) {
                    mma_bf16(acc[mt][2 * ntp],     a[mt], b0, b2);
                    mma_bf16(acc[mt][2 * ntp + 1], a[mt], b1, b3);
                }
            }
        }
    }

    // Epilogue (validated mapping)
    int quad = lane >> 2;
    int tq   = lane & 3;
#pragma unroll
    for (int mt = 0; mt < 2; mt++) {
        int m = row0 + wm * 32 + mt * 16 + quad;
        int b   = m / HWn;
        int pix = m % HWn;
        float* ob = out + (size_t)b * On * HWn;
#pragma unroll
        for (int nt = 0; nt < 8; nt++) {
            int o = col0 + wn * 64 + nt * 8 + tq * 2;
            float b0v = __ldg(bias + o);
            float b1v = __ldg(bias + o + 1);
            float* p0 = ob + (size_t)o * HWn + pix;
            float* p1 = ob + (size_t)(o + 1) * HWn + pix;
            p0[0] = acc[mt][nt][0] + b0v;
            p1[0] = acc[mt][nt][1] + b1v;
            p0[8] = acc[mt][nt][2] + b0v;
            p1[8] = acc[mt][nt][3] + b1v;
        }
    }
}

// ---------------------------------------------------------------------------
// Launch
// ---------------------------------------------------------------------------
extern "C" void kernel_launch(void* const* d_in, const int* in_sizes, int n_in,
                              void* d_out, int out_size)
{
    const float* x        = (const float*)d_in[0];
    const float* offset_w = (const float*)d_in[1];
    const float* offset_b = (const float*)d_in[2];
    const float* mask_w   = (const float*)d_in[3];
    const float* mask_b   = (const float*)d_in[4];
    const float* weight   = (const float*)d_in[5];
    const float* bias     = (const float*)d_in[6];
    float* out = (float*)d_out;

    cudaFuncSetAttribute(offmask_kernel,
                         cudaFuncAttributeMaxDynamicSharedMemorySize, WS1_BYTES);
    cudaFuncSetAttribute(gemm_kernel,
                         cudaFuncAttributeMaxDynamicSharedMemorySize, GEMM_SMEM);

    prep_w<<<(On * CKn + 255) / 256, 256>>>(weight);
    transpose_x<<<dim3(HWn / 32, Cn / 32, Bn), 256>>>(x);
    offmask_kernel<<<(Bn * HWn / 2) / 256, 256, WS1_BYTES>>>(
        x, offset_w, offset_b, mask_w, mask_b);
    gather_kernel<<<Bn * Hn * 3, 256>>>();
    dim3 grid(On / BN, MTOT / BM);
    gemm_kernel<<<grid, 256, GEMM_SMEM>>>(bias, out);
}

// round 13
// speedup vs baseline: 2.1386x; 1.1740x over previous
#include <cuda_runtime.h>
#include <cuda_bf16.h>
#include <cuda_fp16.h>
#include <math.h>
#include <cstdint>

// Problem constants
static constexpr int Bn = 8;
static constexpr int Cn = 128;
static constexpr int On = 256;
static constexpr int Hn = 96;
static constexpr int Wn = 96;
static constexpr int HWn = Hn * Wn;        // 9216
static constexpr int KKn = 9;
static constexpr int CKn = Cn * KKn;       // 1152
static constexpr int NCH = 27;
static constexpr int KP  = 2 * CKn;        // 2304: interleaved fp16 [hi,lo] pairs
static constexpr int MTOT = Bn * HWn;      // 73728
static constexpr int BM = 128, BN = 128, BK = 64;
static constexpr int NST = KP / BK;        // 36

// Scratch
__device__ float  g_offmask[Bn * NCH * HWn];
__device__ float  g_xt[(size_t)Bn * HWn * Cn];   // x transposed to NHWC
__device__ __half g_A2[(size_t)MTOT * KP];       // im2col, K: (k*128+c) -> {hi,lo}
__device__ __half g_B2[(size_t)On * KP];         // weights, same K layout

// ---------------------------------------------------------------------------
// PTX helpers
// ---------------------------------------------------------------------------
__device__ __forceinline__ uint32_t smem_u32(const void* p) {
    uint32_t a;
    asm("{ .reg .u64 t; cvta.to.shared.u64 t, %1; cvt.u32.u64 %0, t; }"
        : "=r"(a) : "l"(p));
    return a;
}
__device__ __forceinline__ void cp_async16(uint32_t dst, const void* src) {
    asm volatile("cp.async.cg.shared.global [%0], [%1], 16;"
                 :: "r"(dst), "l"(src) : "memory");
}
#define CP_COMMIT() asm volatile("cp.async.commit_group;" ::: "memory")
#define CP_WAIT1()  asm volatile("cp.async.wait_group 1;" ::: "memory")

__device__ __forceinline__ void ldmx4(uint32_t& r0, uint32_t& r1,
                                      uint32_t& r2, uint32_t& r3, uint32_t addr) {
    asm volatile("ldmatrix.sync.aligned.m8n8.x4.shared.b16 {%0,%1,%2,%3}, [%4];"
                 : "=r"(r0), "=r"(r1), "=r"(r2), "=r"(r3) : "r"(addr));
}
__device__ __forceinline__ void mma_fp16(float* c, const uint32_t* a,
                                         uint32_t b0, uint32_t b1) {
    asm volatile(
        "mma.sync.aligned.m16n8k16.row.col.f32.f16.f16.f32 "
        "{%0,%1,%2,%3}, {%4,%5,%6,%7}, {%8,%9}, {%0,%1,%2,%3};"
        : "+f"(c[0]), "+f"(c[1]), "+f"(c[2]), "+f"(c[3])
        : "r"(a[0]), "r"(a[1]), "r"(a[2]), "r"(a[3]), "r"(b0), "r"(b1));
}

// ---------------------------------------------------------------------------
// Kernel: x NCHW -> NHWC (tiled 32x32 smem transpose)
// ---------------------------------------------------------------------------
__global__ void __launch_bounds__(256) transpose_x(const float* __restrict__ x)
{
    __shared__ float t[32][33];
    int b  = blockIdx.z;
    int c0 = blockIdx.y * 32;
    int hw0 = blockIdx.x * 32;
    int tid = threadIdx.x;
    int lx = tid & 31, ly = tid >> 5;

    const float* xb = x + ((size_t)b * Cn + c0) * HWn + hw0;
#pragma unroll
    for (int i = 0; i < 4; i++) {
        int c = ly + i * 8;
        t[c][lx] = xb[(size_t)c * HWn + lx];
    }
    __syncthreads();
    float* xtb = g_xt + ((size_t)b * HWn + hw0) * Cn + c0;
#pragma unroll
    for (int i = 0; i < 4; i++) {
        int hw = ly + i * 8;
        xtb[(size_t)hw * Cn + lx] = t[lx][hw];
    }
}

// ---------------------------------------------------------------------------
// Kernel: weight -> fp16 hi/lo interleaved, K index 2*(k*128+c){+1}
// ---------------------------------------------------------------------------
__global__ void prep_w(const float* __restrict__ w) {
    int i = blockIdx.x * 256 + threadIdx.x;
    if (i < On * CKn) {
        int o = i / CKn, r = i % CKn;
        int c = r / 9, k = r % 9;
        int ckp = k * Cn + c;
        float v = w[i];
        __half hi = __float2half_rn(v);
        __half lo = __float2half_rn(v - __half2float(hi));
        __half* row = g_B2 + (size_t)o * KP;
        row[2 * ckp]     = hi;
        row[2 * ckp + 1] = lo;
    }
}

// ---------------------------------------------------------------------------
// Kernel: offset + mask 3x3 conv (27 channels), fp32 direct.
// 2 pixels/thread (batch b and b+4): one smem weight read feeds both.
// ---------------------------------------------------------------------------
static constexpr int WS1_FLOATS = NCH * Cn * 12;
static constexpr int WS1_BYTES  = WS1_FLOATS * 4;

__global__ void __launch_bounds__(256) offmask_kernel(
    const float* __restrict__ x,
    const float* __restrict__ off_w, const float* __restrict__ off_b,
    const float* __restrict__ msk_w, const float* __restrict__ msk_b)
{
    extern __shared__ float ws[];
    int tid = threadIdx.x;
    for (int i = tid; i < WS1_FLOATS; i += 256) {
        int tap = i % 12;
        int c   = (i / 12) % Cn;
        int ch  = i / (12 * Cn);
        float v = 0.0f;
        if (tap < 9)
            v = (ch < 18) ? off_w[(ch * Cn + c) * 9 + tap]
                          : msk_w[((ch - 18) * Cn + c) * 9 + tap];
        ws[i] = v;
    }
    __syncthreads();

    int g = blockIdx.x * 256 + tid;       // 0 .. MTOT/2-1
    int b   = g / HWn;                    // 0..3
    int pix = g % HWn;
    int oh  = pix / Wn;
    int owp = pix % Wn;

    int  offs[9];
    bool valt[9];
#pragma unroll
    for (int kh = 0; kh < 3; kh++)
#pragma unroll
        for (int kw = 0; kw < 3; kw++) {
            int y  = oh - 1 + kh;
            int xx = owp - 1 + kw;
            bool v = (y >= 0 && y < Hn && xx >= 0 && xx < Wn);
            valt[kh * 3 + kw] = v;
            offs[kh * 3 + kw] = v ? (y * Wn + xx) : 0;
        }

    float acc0[NCH], acc1[NCH];
#pragma unroll
    for (int ch = 0; ch < NCH; ch++) {
        float bv = (ch < 18) ? off_b[ch] : msk_b[ch - 18];
        acc0[ch] = bv;
        acc1[ch] = bv;
    }

    const float* xb0 = x + (size_t)b * Cn * HWn;
    const float* xb1 = xb0 + (size_t)4 * Cn * HWn;
    for (int c = 0; c < Cn; c++) {
        float xv0[9], xv1[9];
        const float* xc0 = xb0 + c * HWn;
        const float* xc1 = xb1 + c * HWn;
#pragma unroll
        for (int j = 0; j < 9; j++) {
            xv0[j] = valt[j] ? xc0[offs[j]] : 0.0f;
            xv1[j] = valt[j] ? xc1[offs[j]] : 0.0f;
        }
#pragma unroll
        for (int ch = 0; ch < NCH; ch++) {
            const float4* wp = (const float4*)&ws[(ch * Cn + c) * 12];
            float4 wa = wp[0];
            float4 wb = wp[1];
            float  w8 = ws[(ch * Cn + c) * 12 + 8];
            acc0[ch] += xv0[0] * wa.x + xv0[1] * wa.y + xv0[2] * wa.z + xv0[3] * wa.w
                      + xv0[4] * wb.x + xv0[5] * wb.y + xv0[6] * wb.z + xv0[7] * wb.w
                      + xv0[8] * w8;
            acc1[ch] += xv1[0] * wa.x + xv1[1] * wa.y + xv1[2] * wa.z + xv1[3] * wa.w
                      + xv1[4] * wb.x + xv1[5] * wb.y + xv1[6] * wb.z + xv1[7] * wb.w
                      + xv1[8] * w8;
        }
    }

    float* dst0 = g_offmask + (size_t)b * NCH * HWn + pix;
    float* dst1 = dst0 + (size_t)4 * NCH * HWn;
#pragma unroll
    for (int ch = 0; ch < NCH; ch++) {
        float v0 = acc0[ch], v1 = acc1[ch];
        if (ch >= 18) {
            v0 = 1.0f / (1.0f + expf(-v0));
            v1 = 1.0f / (1.0f + expf(-v1));
        }
        dst0[ch * HWn] = v0;
        dst1[ch * HWn] = v1;
    }
}

// ---------------------------------------------------------------------------
// Kernel: bilinear gather -> A2, fp16 hi/lo interleaved (half2 stores).
// NHWC x: each (px,tap) corner is 128 consecutive floats.
// ---------------------------------------------------------------------------
__global__ void __launch_bounds__(256) gather_kernel()
{
    __shared__ float4 mw4[32 * KKn];     // [p*9+k]
    __shared__ int4   mo4[32 * KKn];

    int blk = blockIdx.x;
    int b   = blk / (Hn * 3);
    int r   = blk % (Hn * 3);
    int oh  = r / 3;
    int ow0 = (r % 3) * 32;
    int tid  = threadIdx.x;
    int wid  = tid >> 5;
    int lane = tid & 31;

    const float* om = g_offmask + (size_t)b * NCH * HWn;
    for (int i = tid; i < 32 * KKn; i += 256) {
        int p = i / KKn;
        int k = i % KKn;
        int pix = oh * Wn + ow0 + p;
        float offy = om[(2 * k) * HWn + pix];
        float offx = om[(2 * k + 1) * HWn + pix];
        float m    = om[(18 + k) * HWn + pix];
        float py = (float)(oh - 1 + k / 3) + offy;
        float px = (float)(ow0 + p - 1 + k % 3) + offx;
        float y0f = floorf(py), x0f = floorf(px);
        int y0 = (int)y0f, x0 = (int)x0f;
        int y1 = y0 + 1,  x1 = x0 + 1;
        float wy1 = py - y0f, wy0 = 1.0f - wy1;
        float wx1 = px - x0f, wx0 = 1.0f - wx1;
        bool vy0 = (y0 >= 0 && y0 < Hn), vy1 = (y1 >= 0 && y1 < Hn);
        bool vx0 = (x0 >= 0 && x0 < Wn), vx1 = (x1 >= 0 && x1 < Wn);
        int cy0 = min(max(y0, 0), Hn - 1), cy1 = min(max(y1, 0), Hn - 1);
        int cx0 = min(max(x0, 0), Wn - 1), cx1 = min(max(x1, 0), Wn - 1);
        mw4[i] = make_float4(
            wy0 * wx0 * m * ((vy0 && vx0) ? 1.0f : 0.0f),
            wy0 * wx1 * m * ((vy0 && vx1) ? 1.0f : 0.0f),
            wy1 * wx0 * m * ((vy1 && vx0) ? 1.0f : 0.0f),
            wy1 * wx1 * m * ((vy1 && vx1) ? 1.0f : 0.0f));
        mo4[i] = make_int4(cy0 * Wn + cx0, cy0 * Wn + cx1,
                           cy1 * Wn + cx0, cy1 * Wn + cx1);
    }
    __syncthreads();

    const float* xtb = g_xt + (size_t)b * HWn * Cn;
    size_t arow0 = ((size_t)b * HWn + oh * Wn + ow0) * KP;

    // 288 (p,k) tasks over 8 warps; lane strides channels
    for (int i = wid; i < 32 * KKn; i += 8) {
        int p = i / KKn;
        int k = i % KKn;
        float4 w = mw4[i];
        int4   o = mo4[i];
        const float* c00 = xtb + (size_t)o.x * Cn;
        const float* c01 = xtb + (size_t)o.y * Cn;
        const float* c10 = xtb + (size_t)o.z * Cn;
        const float* c11 = xtb + (size_t)o.w * Cn;
        __half2* dst = (__half2*)(g_A2 + arow0 + (size_t)p * KP) + k * Cn;
#pragma unroll
        for (int it = 0; it < 4; it++) {
            int c = it * 32 + lane;
            float v = w.x * c00[c] + w.y * c01[c]
                    + w.z * c10[c] + w.w * c11[c];
            __half hi = __float2half_rn(v);
            __half lo = __float2half_rn(v - __half2float(hi));
            dst[c] = __halves2half2(hi, lo);
        }
    }
}

// ---------------------------------------------------------------------------
// Kernel: fp16 HMMA GEMM, CTA 128x128, BK=64, 3-stage cp.async pipeline.
// K'=2304 (2-term fp16 split, hi/lo interleaved; A and B share the layout).
// Grid (N=2, M=576): A tile L2 reuse.
// ---------------------------------------------------------------------------
static constexpr int PITCH  = 144;
static constexpr int ABYTES = BM * PITCH;         // 18432
static constexpr int BUFB   = 2 * ABYTES;         // 36864
static constexpr int GEMM_SMEM = 3 * BUFB;        // 110592

__global__ void __launch_bounds__(256, 2) gemm_kernel(
    const float* __restrict__ bias, float* __restrict__ out)
{
    extern __shared__ __align__(16) char sm[];
    uint32_t sb = smem_u32(sm);
    int tid  = threadIdx.x;
    int wid  = tid >> 5;
    int lane = tid & 31;
    int wm = wid & 3;
    int wn = wid >> 2;

    int row0 = blockIdx.y * BM;
    int col0 = blockIdx.x * BN;

    auto load_stage = [&](int s) {
        int kc = s * BK;
        uint32_t dst = sb + (s % 3) * BUFB;
#pragma unroll
        for (int i = 0; i < 4; i++) {
            int ch = tid + i * 256;
            int r = ch >> 3, u = ch & 7;
            cp_async16(dst + r * PITCH + u * 16,
                       g_A2 + (size_t)(row0 + r) * KP + kc + u * 8);
        }
        uint32_t dstb = dst + ABYTES;
#pragma unroll
        for (int i = 0; i < 4; i++) {
            int ch = tid + i * 256;
            int r = ch >> 3, u = ch & 7;
            cp_async16(dstb + r * PITCH + u * 16,
                       g_B2 + (size_t)(col0 + r) * KP + kc + u * 8);
        }
        CP_COMMIT();
    };

    float acc[2][8][4];
#pragma unroll
    for (int mt = 0; mt < 2; mt++)
#pragma unroll
        for (int nt = 0; nt < 8; nt++)
#pragma unroll
            for (int e = 0; e < 4; e++) acc[mt][nt][e] = 0.0f;

    load_stage(0);
    load_stage(1);

    int lrow = lane & 15;
    int lcol = (lane >> 4) * 8;

    for (int s = 0; s < NST; s++) {
        CP_WAIT1();
        __syncthreads();
        if (s + 2 < NST) load_stage(s + 2);

        uint32_t bufA = sb + (s % 3) * BUFB;
        uint32_t bufB = bufA + ABYTES;

#pragma unroll
        for (int kk = 0; kk < 4; kk++) {
            int colb = (kk * 16 + lcol) * 2;
            uint32_t a[2][4];
#pragma unroll
            for (int mt = 0; mt < 2; mt++) {
                int row = wm * 32 + mt * 16 + lrow;
                ldmx4(a[mt][0], a[mt][1], a[mt][2], a[mt][3],
                      bufA + row * PITCH + colb);
            }
#pragma unroll
            for (int ntp = 0; ntp < 4; ntp++) {
                int row = wn * 64 + ntp * 16 + lrow;
                uint32_t b0, b1, b2, b3;
                ldmx4(b0, b1, b2, b3, bufB + row * PITCH + colb);
#pragma unroll
                for (int mt = 0; mt < 2; mt++) {
                    mma_fp16(acc[mt][2 * ntp],     a[mt], b0, b2);
                    mma_fp16(acc[mt][2 * ntp + 1], a[mt], b1, b3);
                }
            }
        }
    }

    // Epilogue (validated mapping)
    int quad = lane >> 2;
    int tq   = lane & 3;
#pragma unroll
    for (int mt = 0; mt < 2; mt++) {
        int m = row0 + wm * 32 + mt * 16 + quad;
        int b   = m / HWn;
        int pix = m % HWn;
        float* ob = out + (size_t)b * On * HWn;
#pragma unroll
        for (int nt = 0; nt < 8; nt++) {
            int o = col0 + wn * 64 + nt * 8 + tq * 2;
            float b0v = __ldg(bias + o);
            float b1v = __ldg(bias + o + 1);
            float* p0 = ob + (size_t)o * HWn + pix;
            float* p1 = ob + (size_t)(o + 1) * HWn + pix;
            p0[0] = acc[mt][nt][0] + b0v;
            p1[0] = acc[mt][nt][1] + b1v;
            p0[8] = acc[mt][nt][2] + b0v;
            p1[8] = acc[mt][nt][3] + b1v;
        }
    }
}

// ---------------------------------------------------------------------------
// Launch
// ---------------------------------------------------------------------------
extern "C" void kernel_launch(void* const* d_in, const int* in_sizes, int n_in,
                              void* d_out, int out_size)
{
    const float* x        = (const float*)d_in[0];
    const float* offset_w = (const float*)d_in[1];
    const float* offset_b = (const float*)d_in[2];
    const float* mask_w   = (const float*)d_in[3];
    const float* mask_b   = (const float*)d_in[4];
    const float* weight   = (const float*)d_in[5];
    const float* bias     = (const float*)d_in[6];
    float* out = (float*)d_out;

    cudaFuncSetAttribute(offmask_kernel,
                         cudaFuncAttributeMaxDynamicSharedMemorySize, WS1_BYTES);
    cudaFuncSetAttribute(gemm_kernel,
                         cudaFuncAttributeMaxDynamicSharedMemorySize, GEMM_SMEM);

    prep_w<<<(On * CKn + 255) / 256, 256>>>(weight);
    transpose_x<<<dim3(HWn / 32, Cn / 32, Bn), 256>>>(x);
    offmask_kernel<<<(Bn * HWn / 2) / 256, 256, WS1_BYTES>>>(
        x, offset_w, offset_b, mask_w, mask_b);
    gather_kernel<<<Bn * Hn * 3, 256>>>();
    dim3 grid(On / BN, MTOT / BM);
    gemm_kernel<<<grid, 256, GEMM_SMEM>>>(bias, out);
}

// round 15
// speedup vs baseline: 2.5963x; 1.2141x over previous
#include <cuda_runtime.h>
#include <cuda_bf16.h>
#include <cuda_fp16.h>
#include <math.h>
#include <cstdint>

// Problem constants
static constexpr int Bn = 8;
static constexpr int Cn = 128;
static constexpr int On = 256;
static constexpr int Hn = 96;
static constexpr int Wn = 96;
static constexpr int HWn = Hn * Wn;        // 9216
static constexpr int KKn = 9;
static constexpr int CKn = Cn * KKn;       // 1152
static constexpr int NCH = 27;
static constexpr int KP  = 2 * CKn;        // 2304: interleaved fp16 [hi,lo]
static constexpr int MTOT = Bn * HWn;      // 73728
static constexpr int BM = 128, BN = 128, BK = 64;
static constexpr int NST = KP / BK;        // 36

// Scratch
__device__ float   g_offmask[Bn * NCH * HWn];
__device__ float   g_xt[(size_t)Bn * HWn * Cn];   // NHWC fp32 (gather)
__device__ __half2 g_xh[(size_t)Bn * HWn * Cn];   // NHWC (hi,lo) fp16 pairs
__device__ __half  g_A2[(size_t)MTOT * KP];       // im2col, (k*128+c)->{hi,lo}
__device__ __half  g_B2[(size_t)On * KP];         // main weights, same layout
__device__ __half  g_B2o[32 * KP];                // offmask weights (27 + pad)

// ---------------------------------------------------------------------------
// PTX helpers
// ---------------------------------------------------------------------------
__device__ __forceinline__ uint32_t smem_u32(const void* p) {
    uint32_t a;
    asm("{ .reg .u64 t; cvta.to.shared.u64 t, %1; cvt.u32.u64 %0, t; }"
        : "=r"(a) : "l"(p));
    return a;
}
__device__ __forceinline__ void cp_async16(uint32_t dst, const void* src) {
    asm volatile("cp.async.cg.shared.global [%0], [%1], 16;"
                 :: "r"(dst), "l"(src) : "memory");
}
__device__ __forceinline__ void cp_async16z(uint32_t dst, const void* src, int sz) {
    asm volatile("cp.async.cg.shared.global [%0], [%1], 16, %2;"
                 :: "r"(dst), "l"(src), "r"(sz) : "memory");
}
#define CP_COMMIT() asm volatile("cp.async.commit_group;" ::: "memory")
#define CP_WAIT1()  asm volatile("cp.async.wait_group 1;" ::: "memory")

__device__ __forceinline__ void ldmx4(uint32_t& r0, uint32_t& r1,
                                      uint32_t& r2, uint32_t& r3, uint32_t addr) {
    asm volatile("ldmatrix.sync.aligned.m8n8.x4.shared.b16 {%0,%1,%2,%3}, [%4];"
                 : "=r"(r0), "=r"(r1), "=r"(r2), "=r"(r3) : "r"(addr));
}
__device__ __forceinline__ void mma_fp16(float* c, const uint32_t* a,
                                         uint32_t b0, uint32_t b1) {
    asm volatile(
        "mma.sync.aligned.m16n8k16.row.col.f32.f16.f16.f32 "
        "{%0,%1,%2,%3}, {%4,%5,%6,%7}, {%8,%9}, {%0,%1,%2,%3};"
        : "+f"(c[0]), "+f"(c[1]), "+f"(c[2]), "+f"(c[3])
        : "r"(a[0]), "r"(a[1]), "r"(a[2]), "r"(a[3]), "r"(b0), "r"(b1));
}

// ---------------------------------------------------------------------------
// transpose: x NCHW -> g_xt (fp32 NHWC) + g_xh (fp16 hi/lo NHWC)
// ---------------------------------------------------------------------------
__global__ void __launch_bounds__(256) transpose_x(const float* __restrict__ x)
{
    __shared__ float t[32][33];
    int b  = blockIdx.z;
    int c0 = blockIdx.y * 32;
    int hw0 = blockIdx.x * 32;
    int tid = threadIdx.x;
    int lx = tid & 31, ly = tid >> 5;

    const float* xb = x + ((size_t)b * Cn + c0) * HWn + hw0;
#pragma unroll
    for (int i = 0; i < 4; i++) {
        int c = ly + i * 8;
        t[c][lx] = xb[(size_t)c * HWn + lx];
    }
    __syncthreads();
    float*   xtb = g_xt + ((size_t)b * HWn + hw0) * Cn + c0;
    __half2* xhb = g_xh + ((size_t)b * HWn + hw0) * Cn + c0;
#pragma unroll
    for (int i = 0; i < 4; i++) {
        int hw = ly + i * 8;
        float v = t[lx][hw];
        xtb[(size_t)hw * Cn + lx] = v;
        __half hi = __float2half_rn(v);
        __half lo = __float2half_rn(v - __half2float(hi));
        xhb[(size_t)hw * Cn + lx] = __halves2half2(hi, lo);
    }
}

// ---------------------------------------------------------------------------
// prep: main weight -> fp16 hi/lo interleaved, K = 2*(k*128+c){+1}
// ---------------------------------------------------------------------------
__global__ void prep_w(const float* __restrict__ w) {
    int i = blockIdx.x * 256 + threadIdx.x;
    if (i < On * CKn) {
        int o = i / CKn, r = i % CKn;
        int c = r / 9, k = r % 9;
        int ckp = k * Cn + c;
        float v = w[i];
        __half hi = __float2half_rn(v);
        __half lo = __float2half_rn(v - __half2float(hi));
        __half* row = g_B2 + (size_t)o * KP;
        row[2 * ckp]     = hi;
        row[2 * ckp + 1] = lo;
    }
}

// prep: offmask weights -> g_B2o [32][KP], rows 27..31 zero
__global__ void prep_wo(const float* __restrict__ off_w,
                        const float* __restrict__ msk_w) {
    int i = blockIdx.x * 256 + threadIdx.x;   // 32*1152
    if (i < 32 * CKn) {
        int ch = i / CKn, r = i % CKn;
        int c = r / 9, k = r % 9;
        float v = 0.0f;
        if (ch < 18)       v = off_w[(ch * Cn + c) * 9 + k];
        else if (ch < 27)  v = msk_w[((ch - 18) * Cn + c) * 9 + k];
        __half hi = __float2half_rn(v);
        __half lo = __float2half_rn(v - __half2float(hi));
        __half* row = g_B2o + (size_t)ch * KP;
        int ckp = k * Cn + c;
        row[2 * ckp]     = hi;
        row[2 * ckp + 1] = lo;
    }
}

// ---------------------------------------------------------------------------
// offmask GEMM: M=73728 (128/CTA), N=32 (27 used), K=2304 fp16 (hi/lo).
// A tile built on the fly from g_xh with tap shifts + zero-fill padding.
// ---------------------------------------------------------------------------
static constexpr int OMP     = 272;               // smem pitch (128 half + pad)
static constexpr int OM_AB   = 128 * OMP;         // 34816
static constexpr int OM_BB   = 32 * OMP;          // 8704
static constexpr int OM_ST   = OM_AB + OM_BB;     // 43520
static constexpr int OM_SMEM = 3 * OM_ST;         // 130560
static constexpr int OM_NST  = KP / 128;          // 18

__global__ void __launch_bounds__(256, 1) offmask_gemm(
    const float* __restrict__ off_b, const float* __restrict__ msk_b)
{
    extern __shared__ __align__(16) char sm[];
    uint32_t sb = smem_u32(sm);
    int tid  = threadIdx.x;
    int wid  = tid >> 5;
    int lane = tid & 31;
    int wm = wid & 3;           // 4 M-warps (32 px)
    int wn = wid >> 2;          // 2 N-warps (16 ch)

    int gm0 = blockIdx.x * 128;
    int b   = gm0 / HWn;
    int hw0 = gm0 % HWn;        // tile stays in one batch (9216 = 72*128)

    // per-thread A-load identity: one pixel, one 128B half-chunk
    int apx = tid >> 1;
    int auh = tid & 1;
    int ahw = hw0 + apx;
    int aoh = ahw / Wn, aow = ahw % Wn;
    const char* xhb = (const char*)g_xh + (size_t)b * HWn * 512;

    auto load_stage = [&](int s) {
        int j  = s >> 1;              // tap 0..8
        int hp = s & 1;               // channel half 0/1
        int kh = j / 3, kw = j % 3;
        int y = aoh + kh - 1, xx = aow + kw - 1;
        bool valid = (y >= 0 && y < Hn && xx >= 0 && xx < Wn);
        int srcpix = valid ? (ahw + (kh - 1) * Wn + (kw - 1)) : ahw;
        const char* src = xhb + (size_t)srcpix * 512 + hp * 256 + auh * 128;
        uint32_t dst = sb + (s % 3) * OM_ST + apx * OMP + auh * 128;
        int sz = valid ? 16 : 0;
#pragma unroll
        for (int i = 0; i < 8; i++)
            cp_async16z(dst + i * 16, src + i * 16, sz);
        // B: 512 16B chunks over 256 threads
        uint32_t bdst = sb + (s % 3) * OM_ST + OM_AB;
#pragma unroll
        for (int q = 0; q < 2; q++) {
            int c = tid + q * 256;
            int row = c >> 4, u = c & 15;
            cp_async16(bdst + row * OMP + u * 16,
                       (const char*)g_B2o + (size_t)row * KP * 2 + s * 256 + u * 16);
        }
        CP_COMMIT();
    };

    float acc[2][2][4];
#pragma unroll
    for (int mt = 0; mt < 2; mt++)
#pragma unroll
        for (int nb = 0; nb < 2; nb++)
#pragma unroll
            for (int e = 0; e < 4; e++) acc[mt][nb][e] = 0.0f;

    load_stage(0);
    load_stage(1);

    int lrow = lane & 15;
    int lcol = (lane >> 4) * 8;

    for (int s = 0; s < OM_NST; s++) {
        CP_WAIT1();
        __syncthreads();
        if (s + 2 < OM_NST) load_stage(s + 2);

        uint32_t bufA = sb + (s % 3) * OM_ST;
        uint32_t bufB = bufA + OM_AB;

#pragma unroll
        for (int kk = 0; kk < 8; kk++) {
            int colb = (kk * 16 + lcol) * 2;
            uint32_t a[2][4];
#pragma unroll
            for (int mt = 0; mt < 2; mt++) {
                int row = wm * 32 + mt * 16 + lrow;
                ldmx4(a[mt][0], a[mt][1], a[mt][2], a[mt][3],
                      bufA + row * OMP + colb);
            }
            uint32_t b0, b1, b2, b3;
            ldmx4(b0, b1, b2, b3, bufB + (wn * 16 + lrow) * OMP + colb);
#pragma unroll
            for (int mt = 0; mt < 2; mt++) {
                mma_fp16(acc[mt][0], a[mt], b0, b2);
                mma_fp16(acc[mt][1], a[mt], b1, b3);
            }
        }
    }

    // Epilogue: bias + sigmoid(mask), store to g_offmask [b][ch][hw]
    int quad = lane >> 2;
    int tq   = lane & 3;
    float* omb = g_offmask + (size_t)b * NCH * HWn;
#pragma unroll
    for (int mt = 0; mt < 2; mt++) {
#pragma unroll
        for (int nb = 0; nb < 2; nb++) {
#pragma unroll
            for (int e = 0; e < 4; e++) {
                int ch = wn * 16 + nb * 8 + tq * 2 + (e & 1);
                if (ch >= NCH) continue;
                int hw = hw0 + wm * 32 + mt * 16 + quad + (e >> 1) * 8;
                float bv = (ch < 18) ? __ldg(off_b + ch) : __ldg(msk_b + ch - 18);
                float v = acc[mt][nb][e] + bv;
                if (ch >= 18) v = 1.0f / (1.0f + expf(-v));
                omb[(size_t)ch * HWn + hw] = v;
            }
        }
    }
}

// ---------------------------------------------------------------------------
// gather: bilinear -> A2 fp16 hi/lo interleaved (unchanged, verified R13)
// ---------------------------------------------------------------------------
__global__ void __launch_bounds__(256) gather_kernel()
{
    __shared__ float4 mw4[32 * KKn];
    __shared__ int4   mo4[32 * KKn];

    int blk = blockIdx.x;
    int b   = blk / (Hn * 3);
    int r   = blk % (Hn * 3);
    int oh  = r / 3;
    int ow0 = (r % 3) * 32;
    int tid  = threadIdx.x;
    int wid  = tid >> 5;
    int lane = tid & 31;

    const float* om = g_offmask + (size_t)b * NCH * HWn;
    for (int i = tid; i < 32 * KKn; i += 256) {
        int p = i / KKn;
        int k = i % KKn;
        int pix = oh * Wn + ow0 + p;
        float offy = om[(2 * k) * HWn + pix];
        float offx = om[(2 * k + 1) * HWn + pix];
        float m    = om[(18 + k) * HWn + pix];
        float py = (float)(oh - 1 + k / 3) + offy;
        float px = (float)(ow0 + p - 1 + k % 3) + offx;
        float y0f = floorf(py), x0f = floorf(px);
        int y0 = (int)y0f, x0 = (int)x0f;
        int y1 = y0 + 1,  x1 = x0 + 1;
        float wy1 = py - y0f, wy0 = 1.0f - wy1;
        float wx1 = px - x0f, wx0 = 1.0f - wx1;
        bool vy0 = (y0 >= 0 && y0 < Hn), vy1 = (y1 >= 0 && y1 < Hn);
        bool vx0 = (x0 >= 0 && x0 < Wn), vx1 = (x1 >= 0 && x1 < Wn);
        int cy0 = min(max(y0, 0), Hn - 1), cy1 = min(max(y1, 0), Hn - 1);
        int cx0 = min(max(x0, 0), Wn - 1), cx1 = min(max(x1, 0), Wn - 1);
        mw4[i] = make_float4(
            wy0 * wx0 * m * ((vy0 && vx0) ? 1.0f : 0.0f),
            wy0 * wx1 * m * ((vy0 && vx1) ? 1.0f : 0.0f),
            wy1 * wx0 * m * ((vy1 && vx0) ? 1.0f : 0.0f),
            wy1 * wx1 * m * ((vy1 && vx1) ? 1.0f : 0.0f));
        mo4[i] = make_int4(cy0 * Wn + cx0, cy0 * Wn + cx1,
                           cy1 * Wn + cx0, cy1 * Wn + cx1);
    }
    __syncthreads();

    const float* xtb = g_xt + (size_t)b * HWn * Cn;
    size_t arow0 = ((size_t)b * HWn + oh * Wn + ow0) * KP;

    for (int i = wid; i < 32 * KKn; i += 8) {
        int p = i / KKn;
        int k = i % KKn;
        float4 w = mw4[i];
        int4   o = mo4[i];
        const float* c00 = xtb + (size_t)o.x * Cn;
        const float* c01 = xtb + (size_t)o.y * Cn;
        const float* c10 = xtb + (size_t)o.z * Cn;
        const float* c11 = xtb + (size_t)o.w * Cn;
        __half2* dst = (__half2*)(g_A2 + arow0 + (size_t)p * KP) + k * Cn;
#pragma unroll
        for (int it = 0; it < 4; it++) {
            int c = it * 32 + lane;
            float v = w.x * c00[c] + w.y * c01[c]
                    + w.z * c10[c] + w.w * c11[c];
            __half hi = __float2half_rn(v);
            __half lo = __float2half_rn(v - __half2float(hi));
            dst[c] = __halves2half2(hi, lo);
        }
    }
}

// ---------------------------------------------------------------------------
// main GEMM: fp16 HMMA, CTA 128x128, BK=64, 3-stage (unchanged, verified R13)
// ---------------------------------------------------------------------------
static constexpr int PITCH  = 144;
static constexpr int ABYTES = BM * PITCH;         // 18432
static constexpr int BUFB   = 2 * ABYTES;         // 36864
static constexpr int GEMM_SMEM = 3 * BUFB;        // 110592

__global__ void __launch_bounds__(256, 2) gemm_kernel(
    const float* __restrict__ bias, float* __restrict__ out)
{
    extern __shared__ __align__(16) char sm[];
    uint32_t sb = smem_u32(sm);
    int tid  = threadIdx.x;
    int wid  = tid >> 5;
    int lane = tid & 31;
    int wm = wid & 3;
    int wn = wid >> 2;

    int row0 = blockIdx.y * BM;
    int col0 = blockIdx.x * BN;

    auto load_stage = [&](int s) {
        int kc = s * BK;
        uint32_t dst = sb + (s % 3) * BUFB;
#pragma unroll
        for (int i = 0; i < 4; i++) {
            int ch = tid + i * 256;
            int r = ch >> 3, u = ch & 7;
            cp_async16(dst + r * PITCH + u * 16,
                       g_A2 + (size_t)(row0 + r) * KP + kc + u * 8);
        }
        uint32_t dstb = dst + ABYTES;
#pragma unroll
        for (int i = 0; i < 4; i++) {
            int ch = tid + i * 256;
            int r = ch >> 3, u = ch & 7;
            cp_async16(dstb + r * PITCH + u * 16,
                       g_B2 + (size_t)(col0 + r) * KP + kc + u * 8);
        }
        CP_COMMIT();
    };

    float acc[2][8][4];
#pragma unroll
    for (int mt = 0; mt < 2; mt++)
#pragma unroll
        for (int nt = 0; nt < 8; nt++)
#pragma unroll
            for (int e = 0; e < 4; e++) acc[mt][nt][e] = 0.0f;

    load_stage(0);
    load_stage(1);

    int lrow = lane & 15;
    int lcol = (lane >> 4) * 8;

    for (int s = 0; s < NST; s++) {
        CP_WAIT1();
        __syncthreads();
        if (s + 2 < NST) load_stage(s + 2);

        uint32_t bufA = sb + (s % 3) * BUFB;
        uint32_t bufB = bufA + ABYTES;

#pragma unroll
        for (int kk = 0; kk < 4; kk++) {
            int colb = (kk * 16 + lcol) * 2;
            uint32_t a[2][4];
#pragma unroll
            for (int mt = 0; mt < 2; mt++) {
                int row = wm * 32 + mt * 16 + lrow;
                ldmx4(a[mt][0], a[mt][1], a[mt][2], a[mt][3],
                      bufA + row * PITCH + colb);
            }
#pragma unroll
            for (int ntp = 0; ntp < 4; ntp++) {
                int row = wn * 64 + ntp * 16 + lrow;
                uint32_t b0, b1, b2, b3;
                ldmx4(b0, b1, b2, b3, bufB + row * PITCH + colb);
#pragma unroll
                for (int mt = 0; mt < 2; mt++) {
                    mma_fp16(acc[mt][2 * ntp],     a[mt], b0, b2);
                    mma_fp16(acc[mt][2 * ntp + 1], a[mt], b1, b3);
                }
            }
        }
    }

    int quad = lane >> 2;
    int tq   = lane & 3;
#pragma unroll
    for (int mt = 0; mt < 2; mt++) {
        int m = row0 + wm * 32 + mt * 16 + quad;
        int b   = m / HWn;
        int pix = m % HWn;
        float* ob = out + (size_t)b * On * HWn;
#pragma unroll
        for (int nt = 0; nt < 8; nt++) {
            int o = col0 + wn * 64 + nt * 8 + tq * 2;
            float b0v = __ldg(bias + o);
            float b1v = __ldg(bias + o + 1);
            float* p0 = ob + (size_t)o * HWn + pix;
            float* p1 = ob + (size_t)(o + 1) * HWn + pix;
            p0[0] = acc[mt][nt][0] + b0v;
            p1[0] = acc[mt][nt][1] + b1v;
            p0[8] = acc[mt][nt][2] + b0v;
            p1[8] = acc[mt][nt][3] + b1v;
        }
    }
}

// ---------------------------------------------------------------------------
// Launch
// ---------------------------------------------------------------------------
extern "C" void kernel_launch(void* const* d_in, const int* in_sizes, int n_in,
                              void* d_out, int out_size)
{
    const float* x        = (const float*)d_in[0];
    const float* offset_w = (const float*)d_in[1];
    const float* offset_b = (const float*)d_in[2];
    const float* mask_w   = (const float*)d_in[3];
    const float* mask_b   = (const float*)d_in[4];
    const float* weight   = (const float*)d_in[5];
    const float* bias     = (const float*)d_in[6];
    float* out = (float*)d_out;

    cudaFuncSetAttribute(gemm_kernel,
                         cudaFuncAttributeMaxDynamicSharedMemorySize, GEMM_SMEM);
    cudaFuncSetAttribute(offmask_gemm,
                         cudaFuncAttributeMaxDynamicSharedMemorySize, OM_SMEM);

    prep_w<<<(On * CKn + 255) / 256, 256>>>(weight);
    prep_wo<<<(32 * CKn + 255) / 256, 256>>>(offset_w, mask_w);
    transpose_x<<<dim3(HWn / 32, Cn / 32, Bn), 256>>>(x);
    offmask_gemm<<<MTOT / 128, 256, OM_SMEM>>>(offset_b, mask_b);
    gather_kernel<<<Bn * Hn * 3, 256>>>();
    dim3 grid(On / BN, MTOT / BM);
    gemm_kernel<<<grid, 256, GEMM_SMEM>>>(bias, out);
}

// round 16
// speedup vs baseline: 2.6728x; 1.0294x over previous
#include <cuda_runtime.h>
#include <cuda_bf16.h>
#include <cuda_fp16.h>
#include <math.h>
#include <cstdint>

// Problem constants
static constexpr int Bn = 8;
static constexpr int Cn = 128;
static constexpr int On = 256;
static constexpr int Hn = 96;
static constexpr int Wn = 96;
static constexpr int HWn = Hn * Wn;        // 9216
static constexpr int KKn = 9;
static constexpr int CKn = Cn * KKn;       // 1152
static constexpr int NCH = 27;
static constexpr int KP  = 2 * CKn;        // 2304: interleaved fp16 [hi,lo]
static constexpr int MTOT = Bn * HWn;      // 73728
static constexpr int BM = 128, BN = 128, BK = 64;
static constexpr int NST = KP / BK;        // 36

// Scratch
__device__ float   g_offmask[Bn * NCH * HWn];
__device__ float   g_xt[(size_t)Bn * HWn * Cn];   // NHWC fp32 (gather)
__device__ __half2 g_xh[(size_t)Bn * HWn * Cn];   // NHWC (hi,lo) fp16 pairs
__device__ __half  g_A2[(size_t)MTOT * KP];       // im2col, (k*128+c)->{hi,lo}
__device__ __half  g_B2[(size_t)On * KP];         // main weights, same layout
__device__ __half  g_B2o[32 * KP];                // offmask weights (27 + pad)

// ---------------------------------------------------------------------------
// PTX helpers
// ---------------------------------------------------------------------------
__device__ __forceinline__ uint32_t smem_u32(const void* p) {
    uint32_t a;
    asm("{ .reg .u64 t; cvta.to.shared.u64 t, %1; cvt.u32.u64 %0, t; }"
        : "=r"(a) : "l"(p));
    return a;
}
__device__ __forceinline__ void cp_async16(uint32_t dst, const void* src) {
    asm volatile("cp.async.cg.shared.global [%0], [%1], 16;"
                 :: "r"(dst), "l"(src) : "memory");
}
__device__ __forceinline__ void cp_async16z(uint32_t dst, const void* src, int sz) {
    asm volatile("cp.async.cg.shared.global [%0], [%1], 16, %2;"
                 :: "r"(dst), "l"(src), "r"(sz) : "memory");
}
#define CP_COMMIT() asm volatile("cp.async.commit_group;" ::: "memory")
#define CP_WAIT1()  asm volatile("cp.async.wait_group 1;" ::: "memory")
#define CP_WAIT0()  asm volatile("cp.async.wait_group 0;" ::: "memory")

__device__ __forceinline__ void ldmx4(uint32_t& r0, uint32_t& r1,
                                      uint32_t& r2, uint32_t& r3, uint32_t addr) {
    asm volatile("ldmatrix.sync.aligned.m8n8.x4.shared.b16 {%0,%1,%2,%3}, [%4];"
                 : "=r"(r0), "=r"(r1), "=r"(r2), "=r"(r3) : "r"(addr));
}
__device__ __forceinline__ void mma_fp16(float* c, const uint32_t* a,
                                         uint32_t b0, uint32_t b1) {
    asm volatile(
        "mma.sync.aligned.m16n8k16.row.col.f32.f16.f16.f32 "
        "{%0,%1,%2,%3}, {%4,%5,%6,%7}, {%8,%9}, {%0,%1,%2,%3};"
        : "+f"(c[0]), "+f"(c[1]), "+f"(c[2]), "+f"(c[3])
        : "r"(a[0]), "r"(a[1]), "r"(a[2]), "r"(a[3]), "r"(b0), "r"(b1));
}

// ---------------------------------------------------------------------------
// transpose: x NCHW -> g_xt (fp32 NHWC) + g_xh (fp16 hi/lo NHWC)
// ---------------------------------------------------------------------------
__global__ void __launch_bounds__(256) transpose_x(const float* __restrict__ x)
{
    __shared__ float t[32][33];
    int b  = blockIdx.z;
    int c0 = blockIdx.y * 32;
    int hw0 = blockIdx.x * 32;
    int tid = threadIdx.x;
    int lx = tid & 31, ly = tid >> 5;

    const float* xb = x + ((size_t)b * Cn + c0) * HWn + hw0;
#pragma unroll
    for (int i = 0; i < 4; i++) {
        int c = ly + i * 8;
        t[c][lx] = xb[(size_t)c * HWn + lx];
    }
    __syncthreads();
    float*   xtb = g_xt + ((size_t)b * HWn + hw0) * Cn + c0;
    __half2* xhb = g_xh + ((size_t)b * HWn + hw0) * Cn + c0;
#pragma unroll
    for (int i = 0; i < 4; i++) {
        int hw = ly + i * 8;
        float v = t[lx][hw];
        xtb[(size_t)hw * Cn + lx] = v;
        __half hi = __float2half_rn(v);
        __half lo = __float2half_rn(v - __half2float(hi));
        xhb[(size_t)hw * Cn + lx] = __halves2half2(hi, lo);
    }
}

// ---------------------------------------------------------------------------
// prep: main weight -> fp16 hi/lo interleaved, K = 2*(k*128+c){+1}
// ---------------------------------------------------------------------------
__global__ void prep_w(const float* __restrict__ w) {
    int i = blockIdx.x * 256 + threadIdx.x;
    if (i < On * CKn) {
        int o = i / CKn, r = i % CKn;
        int c = r / 9, k = r % 9;
        int ckp = k * Cn + c;
        float v = w[i];
        __half hi = __float2half_rn(v);
        __half lo = __float2half_rn(v - __half2float(hi));
        __half* row = g_B2 + (size_t)o * KP;
        row[2 * ckp]     = hi;
        row[2 * ckp + 1] = lo;
    }
}

// prep: offmask weights -> g_B2o [32][KP], rows 27..31 zero
__global__ void prep_wo(const float* __restrict__ off_w,
                        const float* __restrict__ msk_w) {
    int i = blockIdx.x * 256 + threadIdx.x;   // 32*1152
    if (i < 32 * CKn) {
        int ch = i / CKn, r = i % CKn;
        int c = r / 9, k = r % 9;
        float v = 0.0f;
        if (ch < 18)       v = off_w[(ch * Cn + c) * 9 + k];
        else if (ch < 27)  v = msk_w[((ch - 18) * Cn + c) * 9 + k];
        __half hi = __float2half_rn(v);
        __half lo = __float2half_rn(v - __half2float(hi));
        __half* row = g_B2o + (size_t)ch * KP;
        int ckp = k * Cn + c;
        row[2 * ckp]     = hi;
        row[2 * ckp + 1] = lo;
    }
}

// ---------------------------------------------------------------------------
// offmask GEMM: M=73728 (128/CTA), N=32 (27 used), K=2304 fp16 (hi/lo).
// v2: 2-stage pipeline (87 KB smem) -> 2 CTAs/SM (was 3-stage / 1 CTA/SM,
// occ 12.3%, latency-exposed).
// ---------------------------------------------------------------------------
static constexpr int OMP     = 272;               // smem pitch (256B row + pad)
static constexpr int OM_AB   = 128 * OMP;         // 34816
static constexpr int OM_BB   = 32 * OMP;          // 8704
static constexpr int OM_ST   = OM_AB + OM_BB;     // 43520
static constexpr int OM_SMEM = 2 * OM_ST;         // 87040
static constexpr int OM_NST  = KP / 128;          // 18

__global__ void __launch_bounds__(256, 2) offmask_gemm(
    const float* __restrict__ off_b, const float* __restrict__ msk_b)
{
    extern __shared__ __align__(16) char sm[];
    uint32_t sb = smem_u32(sm);
    int tid  = threadIdx.x;
    int wid  = tid >> 5;
    int lane = tid & 31;
    int wm = wid & 3;           // 4 M-warps (32 px)
    int wn = wid >> 2;          // 2 N-warps (16 ch)

    int gm0 = blockIdx.x * 128;
    int b   = gm0 / HWn;
    int hw0 = gm0 % HWn;        // tile stays in one batch (9216 = 72*128)

    // per-thread A-load identity: one pixel, one 128B half-chunk
    int apx = tid >> 1;
    int auh = tid & 1;
    int ahw = hw0 + apx;
    int aoh = ahw / Wn, aow = ahw % Wn;
    const char* xhb = (const char*)g_xh + (size_t)b * HWn * 512;

    auto load_stage = [&](int s) {
        int j  = s >> 1;              // tap 0..8
        int hp = s & 1;               // channel half 0/1
        int kh = j / 3, kw = j % 3;
        int y = aoh + kh - 1, xx = aow + kw - 1;
        bool valid = (y >= 0 && y < Hn && xx >= 0 && xx < Wn);
        int srcpix = valid ? (ahw + (kh - 1) * Wn + (kw - 1)) : ahw;
        const char* src = xhb + (size_t)srcpix * 512 + hp * 256 + auh * 128;
        uint32_t dst = sb + (s & 1) * OM_ST + apx * OMP + auh * 128;
        int sz = valid ? 16 : 0;
#pragma unroll
        for (int i = 0; i < 8; i++)
            cp_async16z(dst + i * 16, src + i * 16, sz);
        // B: 512 16B chunks over 256 threads
        uint32_t bdst = sb + (s & 1) * OM_ST + OM_AB;
#pragma unroll
        for (int q = 0; q < 2; q++) {
            int c = tid + q * 256;
            int row = c >> 4, u = c & 15;
            cp_async16(bdst + row * OMP + u * 16,
                       (const char*)g_B2o + (size_t)row * KP * 2 + s * 256 + u * 16);
        }
        CP_COMMIT();
    };

    float acc[2][2][4];
#pragma unroll
    for (int mt = 0; mt < 2; mt++)
#pragma unroll
        for (int nb = 0; nb < 2; nb++)
#pragma unroll
            for (int e = 0; e < 4; e++) acc[mt][nb][e] = 0.0f;

    load_stage(0);

    int lrow = lane & 15;
    int lcol = (lane >> 4) * 8;

    for (int s = 0; s < OM_NST; s++) {
        if (s + 1 < OM_NST) { load_stage(s + 1); CP_WAIT1(); }
        else                { CP_WAIT0(); }
        __syncthreads();

        uint32_t bufA = sb + (s & 1) * OM_ST;
        uint32_t bufB = bufA + OM_AB;

#pragma unroll
        for (int kk = 0; kk < 8; kk++) {
            int colb = (kk * 16 + lcol) * 2;
            uint32_t a[2][4];
#pragma unroll
            for (int mt = 0; mt < 2; mt++) {
                int row = wm * 32 + mt * 16 + lrow;
                ldmx4(a[mt][0], a[mt][1], a[mt][2], a[mt][3],
                      bufA + row * OMP + colb);
            }
            uint32_t b0, b1, b2, b3;
            ldmx4(b0, b1, b2, b3, bufB + (wn * 16 + lrow) * OMP + colb);
#pragma unroll
            for (int mt = 0; mt < 2; mt++) {
                mma_fp16(acc[mt][0], a[mt], b0, b2);
                mma_fp16(acc[mt][1], a[mt], b1, b3);
            }
        }
        __syncthreads();
    }

    // Epilogue: bias + sigmoid(mask), store to g_offmask [b][ch][hw]
    int quad = lane >> 2;
    int tq   = lane & 3;
    float* omb = g_offmask + (size_t)b * NCH * HWn;
#pragma unroll
    for (int mt = 0; mt < 2; mt++) {
#pragma unroll
        for (int nb = 0; nb < 2; nb++) {
#pragma unroll
            for (int e = 0; e < 4; e++) {
                int ch = wn * 16 + nb * 8 + tq * 2 + (e & 1);
                if (ch >= NCH) continue;
                int hw = hw0 + wm * 32 + mt * 16 + quad + (e >> 1) * 8;
                float bv = (ch < 18) ? __ldg(off_b + ch) : __ldg(msk_b + ch - 18);
                float v = acc[mt][nb][e] + bv;
                if (ch >= 18) v = 1.0f / (1.0f + expf(-v));
                omb[(size_t)ch * HWn + hw] = v;
            }
        }
    }
}

// ---------------------------------------------------------------------------
// gather: bilinear -> A2 fp16 hi/lo interleaved (unchanged, verified R13)
// ---------------------------------------------------------------------------
__global__ void __launch_bounds__(256) gather_kernel()
{
    __shared__ float4 mw4[32 * KKn];
    __shared__ int4   mo4[32 * KKn];

    int blk = blockIdx.x;
    int b   = blk / (Hn * 3);
    int r   = blk % (Hn * 3);
    int oh  = r / 3;
    int ow0 = (r % 3) * 32;
    int tid  = threadIdx.x;
    int wid  = tid >> 5;
    int lane = tid & 31;

    const float* om = g_offmask + (size_t)b * NCH * HWn;
    for (int i = tid; i < 32 * KKn; i += 256) {
        int p = i / KKn;
        int k = i % KKn;
        int pix = oh * Wn + ow0 + p;
        float offy = om[(2 * k) * HWn + pix];
        float offx = om[(2 * k + 1) * HWn + pix];
        float m    = om[(18 + k) * HWn + pix];
        float py = (float)(oh - 1 + k / 3) + offy;
        float px = (float)(ow0 + p - 1 + k % 3) + offx;
        float y0f = floorf(py), x0f = floorf(px);
        int y0 = (int)y0f, x0 = (int)x0f;
        int y1 = y0 + 1,  x1 = x0 + 1;
        float wy1 = py - y0f, wy0 = 1.0f - wy1;
        float wx1 = px - x0f, wx0 = 1.0f - wx1;
        bool vy0 = (y0 >= 0 && y0 < Hn), vy1 = (y1 >= 0 && y1 < Hn);
        bool vx0 = (x0 >= 0 && x0 < Wn), vx1 = (x1 >= 0 && x1 < Wn);
        int cy0 = min(max(y0, 0), Hn - 1), cy1 = min(max(y1, 0), Hn - 1);
        int cx0 = min(max(x0, 0), Wn - 1), cx1 = min(max(x1, 0), Wn - 1);
        mw4[i] = make_float4(
            wy0 * wx0 * m * ((vy0 && vx0) ? 1.0f : 0.0f),
            wy0 * wx1 * m * ((vy0 && vx1) ? 1.0f : 0.0f),
            wy1 * wx0 * m * ((vy1 && vx0) ? 1.0f : 0.0f),
            wy1 * wx1 * m * ((vy1 && vx1) ? 1.0f : 0.0f));
        mo4[i] = make_int4(cy0 * Wn + cx0, cy0 * Wn + cx1,
                           cy1 * Wn + cx0, cy1 * Wn + cx1);
    }
    __syncthreads();

    const float* xtb = g_xt + (size_t)b * HWn * Cn;
    size_t arow0 = ((size_t)b * HWn + oh * Wn + ow0) * KP;

    for (int i = wid; i < 32 * KKn; i += 8) {
        int p = i / KKn;
        int k = i % KKn;
        float4 w = mw4[i];
        int4   o = mo4[i];
        const float* c00 = xtb + (size_t)o.x * Cn;
        const float* c01 = xtb + (size_t)o.y * Cn;
        const float* c10 = xtb + (size_t)o.z * Cn;
        const float* c11 = xtb + (size_t)o.w * Cn;
        __half2* dst = (__half2*)(g_A2 + arow0 + (size_t)p * KP) + k * Cn;
#pragma unroll
        for (int it = 0; it < 4; it++) {
            int c = it * 32 + lane;
            float v = w.x * c00[c] + w.y * c01[c]
                    + w.z * c10[c] + w.w * c11[c];
            __half hi = __float2half_rn(v);
            __half lo = __float2half_rn(v - __half2float(hi));
            dst[c] = __halves2half2(hi, lo);
        }
    }
}

// ---------------------------------------------------------------------------
// main GEMM: fp16 HMMA, CTA 128x128, BK=64, 3-stage (unchanged, verified R13)
// ---------------------------------------------------------------------------
static constexpr int PITCH  = 144;
static constexpr int ABYTES = BM * PITCH;         // 18432
static constexpr int BUFB   = 2 * ABYTES;         // 36864
static constexpr int GEMM_SMEM = 3 * BUFB;        // 110592

__global__ void __launch_bounds__(256, 2) gemm_kernel(
    const float* __restrict__ bias, float* __restrict__ out)
{
    extern __shared__ __align__(16) char sm[];
    uint32_t sb = smem_u32(sm);
    int tid  = threadIdx.x;
    int wid  = tid >> 5;
    int lane = tid & 31;
    int wm = wid & 3;
    int wn = wid >> 2;

    int row0 = blockIdx.y * BM;
    int col0 = blockIdx.x * BN;

    auto load_stage = [&](int s) {
        int kc = s * BK;
        uint32_t dst = sb + (s % 3) * BUFB;
#pragma unroll
        for (int i = 0; i < 4; i++) {
            int ch = tid + i * 256;
            int r = ch >> 3, u = ch & 7;
            cp_async16(dst + r * PITCH + u * 16,
                       g_A2 + (size_t)(row0 + r) * KP + kc + u * 8);
        }
        uint32_t dstb = dst + ABYTES;
#pragma unroll
        for (int i = 0; i < 4; i++) {
            int ch = tid + i * 256;
            int r = ch >> 3, u = ch & 7;
            cp_async16(dstb + r * PITCH + u * 16,
                       g_B2 + (size_t)(col0 + r) * KP + kc + u * 8);
        }
        CP_COMMIT();
    };

    float acc[2][8][4];
#pragma unroll
    for (int mt = 0; mt < 2; mt++)
#pragma unroll
        for (int nt = 0; nt < 8; nt++)
#pragma unroll
            for (int e = 0; e < 4; e++) acc[mt][nt][e] = 0.0f;

    load_stage(0);
    load_stage(1);

    int lrow = lane & 15;
    int lcol = (lane >> 4) * 8;

    for (int s = 0; s < NST; s++) {
        CP_WAIT1();
        __syncthreads();
        if (s + 2 < NST) load_stage(s + 2);

        uint32_t bufA = sb + (s % 3) * BUFB;
        uint32_t bufB = bufA + ABYTES;

#pragma unroll
        for (int kk = 0; kk < 4; kk++) {
            int colb = (kk * 16 + lcol) * 2;
            uint32_t a[2][4];
#pragma unroll
            for (int mt = 0; mt < 2; mt++) {
                int row = wm * 32 + mt * 16 + lrow;
                ldmx4(a[mt][0], a[mt][1], a[mt][2], a[mt][3],
                      bufA + row * PITCH + colb);
            }
#pragma unroll
            for (int ntp = 0; ntp < 4; ntp++) {
                int row = wn * 64 + ntp * 16 + lrow;
                uint32_t b0, b1, b2, b3;
                ldmx4(b0, b1, b2, b3, bufB + row * PITCH + colb);
#pragma unroll
                for (int mt = 0; mt < 2; mt++) {
                    mma_fp16(acc[mt][2 * ntp],     a[mt], b0, b2);
                    mma_fp16(acc[mt][2 * ntp + 1], a[mt], b1, b3);
                }
            }
        }
    }

    int quad = lane >> 2;
    int tq   = lane & 3;
#pragma unroll
    for (int mt = 0; mt < 2; mt++) {
        int m = row0 + wm * 32 + mt * 16 + quad;
        int b   = m / HWn;
        int pix = m % HWn;
        float* ob = out + (size_t)b * On * HWn;
#pragma unroll
        for (int nt = 0; nt < 8; nt++) {
            int o = col0 + wn * 64 + nt * 8 + tq * 2;
            float b0v = __ldg(bias + o);
            float b1v = __ldg(bias + o + 1);
            float* p0 = ob + (size_t)o * HWn + pix;
            float* p1 = ob + (size_t)(o + 1) * HWn + pix;
            p0[0] = acc[mt][nt][0] + b0v;
            p1[0] = acc[mt][nt][1] + b1v;
            p0[8] = acc[mt][nt][2] + b0v;
            p1[8] = acc[mt][nt][3] + b1v;
        }
    }
}

// ---------------------------------------------------------------------------
// Launch
// ---------------------------------------------------------------------------
extern "C" void kernel_launch(void* const* d_in, const int* in_sizes, int n_in,
                              void* d_out, int out_size)
{
    const float* x        = (const float*)d_in[0];
    const float* offset_w = (const float*)d_in[1];
    const float* offset_b = (const float*)d_in[2];
    const float* mask_w   = (const float*)d_in[3];
    const float* mask_b   = (const float*)d_in[4];
    const float* weight   = (const float*)d_in[5];
    const float* bias     = (const float*)d_in[6];
    float* out = (float*)d_out;

    cudaFuncSetAttribute(gemm_kernel,
                         cudaFuncAttributeMaxDynamicSharedMemorySize, GEMM_SMEM);
    cudaFuncSetAttribute(offmask_gemm,
                         cudaFuncAttributeMaxDynamicSharedMemorySize, OM_SMEM);

    prep_w<<<(On * CKn + 255) / 256, 256>>>(weight);
    prep_wo<<<(32 * CKn + 255) / 256, 256>>>(offset_w, mask_w);
    transpose_x<<<dim3(HWn / 32, Cn / 32, Bn), 256>>>(x);
    offmask_gemm<<<MTOT / 128, 256, OM_SMEM>>>(offset_b, mask_b);
    gather_kernel<<<Bn * Hn * 3, 256>>>();
    dim3 grid(On / BN, MTOT / BM);
    gemm_kernel<<<grid, 256, GEMM_SMEM>>>(bias, out);
}

// round 17
// speedup vs baseline: 2.7777x; 1.0392x over previous
#include <cuda_runtime.h>
#include <cuda_bf16.h>
#include <cuda_fp16.h>
#include <math.h>
#include <cstdint>

// Problem constants
static constexpr int Bn = 8;
static constexpr int Cn = 128;
static constexpr int On = 256;
static constexpr int Hn = 96;
static constexpr int Wn = 96;
static constexpr int HWn = Hn * Wn;        // 9216
static constexpr int KKn = 9;
static constexpr int CKn = Cn * KKn;       // 1152
static constexpr int NCH = 27;
static constexpr int KP  = 2 * CKn;        // 2304: interleaved fp16 [hi,lo]
static constexpr int MTOT = Bn * HWn;      // 73728
static constexpr int BM = 128, BN = 128, BK = 64;
static constexpr int NST = KP / BK;        // 36

// Scratch
__device__ float   g_offmask[Bn * NCH * HWn];
__device__ float   g_xt[(size_t)Bn * HWn * Cn];   // NHWC fp32 (gather)
__device__ __half2 g_xh[(size_t)Bn * HWn * Cn];   // NHWC (hi,lo) fp16 pairs
__device__ __half  g_A2[(size_t)MTOT * KP];       // im2col, (k*128+c)->{hi,lo}
__device__ __half  g_B2[(size_t)On * KP];         // main weights, same layout
__device__ __half  g_B2o[32 * KP];                // offmask weights (27 + pad)

// ---------------------------------------------------------------------------
// PTX helpers
// ---------------------------------------------------------------------------
__device__ __forceinline__ uint32_t smem_u32(const void* p) {
    uint32_t a;
    asm("{ .reg .u64 t; cvta.to.shared.u64 t, %1; cvt.u32.u64 %0, t; }"
        : "=r"(a) : "l"(p));
    return a;
}
__device__ __forceinline__ void cp_async16(uint32_t dst, const void* src) {
    asm volatile("cp.async.cg.shared.global [%0], [%1], 16;"
                 :: "r"(dst), "l"(src) : "memory");
}
__device__ __forceinline__ void cp_async16z(uint32_t dst, const void* src, int sz) {
    asm volatile("cp.async.cg.shared.global [%0], [%1], 16, %2;"
                 :: "r"(dst), "l"(src), "r"(sz) : "memory");
}
#define CP_COMMIT() asm volatile("cp.async.commit_group;" ::: "memory")
#define CP_WAIT1()  asm volatile("cp.async.wait_group 1;" ::: "memory")
#define CP_WAIT0()  asm volatile("cp.async.wait_group 0;" ::: "memory")

__device__ __forceinline__ void ldmx4(uint32_t& r0, uint32_t& r1,
                                      uint32_t& r2, uint32_t& r3, uint32_t addr) {
    asm volatile("ldmatrix.sync.aligned.m8n8.x4.shared.b16 {%0,%1,%2,%3}, [%4];"
                 : "=r"(r0), "=r"(r1), "=r"(r2), "=r"(r3) : "r"(addr));
}
__device__ __forceinline__ void mma_fp16(float* c, const uint32_t* a,
                                         uint32_t b0, uint32_t b1) {
    asm volatile(
        "mma.sync.aligned.m16n8k16.row.col.f32.f16.f16.f32 "
        "{%0,%1,%2,%3}, {%4,%5,%6,%7}, {%8,%9}, {%0,%1,%2,%3};"
        : "+f"(c[0]), "+f"(c[1]), "+f"(c[2]), "+f"(c[3])
        : "r"(a[0]), "r"(a[1]), "r"(a[2]), "r"(a[3]), "r"(b0), "r"(b1));
}

// ---------------------------------------------------------------------------
// transpose: x NCHW -> g_xt (fp32 NHWC) + g_xh (fp16 hi/lo NHWC)
// ---------------------------------------------------------------------------
__global__ void __launch_bounds__(256) transpose_x(const float* __restrict__ x)
{
    __shared__ float t[32][33];
    int b  = blockIdx.z;
    int c0 = blockIdx.y * 32;
    int hw0 = blockIdx.x * 32;
    int tid = threadIdx.x;
    int lx = tid & 31, ly = tid >> 5;

    const float* xb = x + ((size_t)b * Cn + c0) * HWn + hw0;
#pragma unroll
    for (int i = 0; i < 4; i++) {
        int c = ly + i * 8;
        t[c][lx] = xb[(size_t)c * HWn + lx];
    }
    __syncthreads();
    float*   xtb = g_xt + ((size_t)b * HWn + hw0) * Cn + c0;
    __half2* xhb = g_xh + ((size_t)b * HWn + hw0) * Cn + c0;
#pragma unroll
    for (int i = 0; i < 4; i++) {
        int hw = ly + i * 8;
        float v = t[lx][hw];
        xtb[(size_t)hw * Cn + lx] = v;
        __half hi = __float2half_rn(v);
        __half lo = __float2half_rn(v - __half2float(hi));
        xhb[(size_t)hw * Cn + lx] = __halves2half2(hi, lo);
    }
}

// ---------------------------------------------------------------------------
// prep: main weight -> fp16 hi/lo interleaved, K = 2*(k*128+c){+1}
// ---------------------------------------------------------------------------
__global__ void prep_w(const float* __restrict__ w) {
    int i = blockIdx.x * 256 + threadIdx.x;
    if (i < On * CKn) {
        int o = i / CKn, r = i % CKn;
        int c = r / 9, k = r % 9;
        int ckp = k * Cn + c;
        float v = w[i];
        __half hi = __float2half_rn(v);
        __half lo = __float2half_rn(v - __half2float(hi));
        __half* row = g_B2 + (size_t)o * KP;
        row[2 * ckp]     = hi;
        row[2 * ckp + 1] = lo;
    }
}

// prep: offmask weights -> g_B2o [32][KP], rows 27..31 zero
__global__ void prep_wo(const float* __restrict__ off_w,
                        const float* __restrict__ msk_w) {
    int i = blockIdx.x * 256 + threadIdx.x;   // 32*1152
    if (i < 32 * CKn) {
        int ch = i / CKn, r = i % CKn;
        int c = r / 9, k = r % 9;
        float v = 0.0f;
        if (ch < 18)       v = off_w[(ch * Cn + c) * 9 + k];
        else if (ch < 27)  v = msk_w[((ch - 18) * Cn + c) * 9 + k];
        __half hi = __float2half_rn(v);
        __half lo = __float2half_rn(v - __half2float(hi));
        __half* row = g_B2o + (size_t)ch * KP;
        int ckp = k * Cn + c;
        row[2 * ckp]     = hi;
        row[2 * ckp + 1] = lo;
    }
}

// ---------------------------------------------------------------------------
// offmask GEMM: M=73728 (128/CTA), N=32 (27 used), K=2304 fp16 (hi/lo).
// v3: 64-half chunks (23 KB/stage), 2-stage, 36 steps -> 46 KB smem ->
// 4 CTAs/SM; cross-CTA overlap hides the per-step load latency.
// ---------------------------------------------------------------------------
static constexpr int OMP     = 144;               // smem pitch (128B data + 16)
static constexpr int OM_AB   = 128 * OMP;         // 18432
static constexpr int OM_BB   = 32 * OMP;          // 4608
static constexpr int OM_ST   = OM_AB + OM_BB;     // 23040
static constexpr int OM_SMEM = 2 * OM_ST;         // 46080
static constexpr int OM_NST  = 36;                // 4608B per px row / 128B

__global__ void __launch_bounds__(256, 4) offmask_gemm(
    const float* __restrict__ off_b, const float* __restrict__ msk_b)
{
    extern __shared__ __align__(16) char sm[];
    uint32_t sb = smem_u32(sm);
    int tid  = threadIdx.x;
    int wid  = tid >> 5;
    int lane = tid & 31;
    int wm = wid & 3;           // 4 M-warps (32 px)
    int wn = wid >> 2;          // 2 N-warps (16 ch)

    int gm0 = blockIdx.x * 128;
    int b   = gm0 / HWn;
    int hw0 = gm0 % HWn;        // tile stays in one batch (9216 = 72*128)

    // per-thread A-load identity: one pixel (pairs), one 64B half-chunk
    int apx = tid >> 1;
    int auh = tid & 1;
    int ahw = hw0 + apx;
    int aoh = ahw / Wn, aow = ahw % Wn;
    const char* xhb = (const char*)g_xh + (size_t)b * HWn * 512;

    auto load_stage = [&](int s) {
        int j = s >> 2;               // tap 0..8
        int q = s & 3;                // 128B quarter of the 512B px row
        int kh = j / 3, kw = j % 3;
        int y = aoh + kh - 1, xx = aow + kw - 1;
        bool valid = (y >= 0 && y < Hn && xx >= 0 && xx < Wn);
        int srcpix = valid ? (ahw + (kh - 1) * Wn + (kw - 1)) : ahw;
        const char* src = xhb + (size_t)srcpix * 512 + q * 128 + auh * 64;
        uint32_t dst = sb + (s & 1) * OM_ST + apx * OMP + auh * 64;
        int sz = valid ? 16 : 0;
#pragma unroll
        for (int i = 0; i < 4; i++)
            cp_async16z(dst + i * 16, src + i * 16, sz);
        // B: 32 rows x 128B = 256 16B chunks over 256 threads
        uint32_t bdst = sb + (s & 1) * OM_ST + OM_AB;
        {
            int row = tid >> 3, u = tid & 7;
            cp_async16(bdst + row * OMP + u * 16,
                       (const char*)g_B2o + (size_t)row * KP * 2 + s * 128 + u * 16);
        }
        CP_COMMIT();
    };

    float acc[2][2][4];
#pragma unroll
    for (int mt = 0; mt < 2; mt++)
#pragma unroll
        for (int nb = 0; nb < 2; nb++)
#pragma unroll
            for (int e = 0; e < 4; e++) acc[mt][nb][e] = 0.0f;

    load_stage(0);

    int lrow = lane & 15;
    int lcol = (lane >> 4) * 8;

    for (int s = 0; s < OM_NST; s++) {
        if (s + 1 < OM_NST) { load_stage(s + 1); CP_WAIT1(); }
        else                { CP_WAIT0(); }
        __syncthreads();

        uint32_t bufA = sb + (s & 1) * OM_ST;
        uint32_t bufB = bufA + OM_AB;

#pragma unroll
        for (int kk = 0; kk < 4; kk++) {
            int colb = (kk * 16 + lcol) * 2;
            uint32_t a[2][4];
#pragma unroll
            for (int mt = 0; mt < 2; mt++) {
                int row = wm * 32 + mt * 16 + lrow;
                ldmx4(a[mt][0], a[mt][1], a[mt][2], a[mt][3],
                      bufA + row * OMP + colb);
            }
            uint32_t b0, b1, b2, b3;
            ldmx4(b0, b1, b2, b3, bufB + (wn * 16 + lrow) * OMP + colb);
#pragma unroll
            for (int mt = 0; mt < 2; mt++) {
                mma_fp16(acc[mt][0], a[mt], b0, b2);
                mma_fp16(acc[mt][1], a[mt], b1, b3);
            }
        }
        __syncthreads();
    }

    // Epilogue: bias + sigmoid(mask), store to g_offmask [b][ch][hw]
    int quad = lane >> 2;
    int tq   = lane & 3;
    float* omb = g_offmask + (size_t)b * NCH * HWn;
#pragma unroll
    for (int mt = 0; mt < 2; mt++) {
#pragma unroll
        for (int nb = 0; nb < 2; nb++) {
#pragma unroll
            for (int e = 0; e < 4; e++) {
                int ch = wn * 16 + nb * 8 + tq * 2 + (e & 1);
                if (ch >= NCH) continue;
                int hw = hw0 + wm * 32 + mt * 16 + quad + (e >> 1) * 8;
                float bv = (ch < 18) ? __ldg(off_b + ch) : __ldg(msk_b + ch - 18);
                float v = acc[mt][nb][e] + bv;
                if (ch >= 18) v = 1.0f / (1.0f + expf(-v));
                omb[(size_t)ch * HWn + hw] = v;
            }
        }
    }
}

// ---------------------------------------------------------------------------
// gather: bilinear -> A2 fp16 hi/lo interleaved (unchanged, verified R13)
// ---------------------------------------------------------------------------
__global__ void __launch_bounds__(256) gather_kernel()
{
    __shared__ float4 mw4[32 * KKn];
    __shared__ int4   mo4[32 * KKn];

    int blk = blockIdx.x;
    int b   = blk / (Hn * 3);
    int r   = blk % (Hn * 3);
    int oh  = r / 3;
    int ow0 = (r % 3) * 32;
    int tid  = threadIdx.x;
    int wid  = tid >> 5;
    int lane = tid & 31;

    const float* om = g_offmask + (size_t)b * NCH * HWn;
    for (int i = tid; i < 32 * KKn; i += 256) {
        int p = i / KKn;
        int k = i % KKn;
        int pix = oh * Wn + ow0 + p;
        float offy = om[(2 * k) * HWn + pix];
        float offx = om[(2 * k + 1) * HWn + pix];
        float m    = om[(18 + k) * HWn + pix];
        float py = (float)(oh - 1 + k / 3) + offy;
        float px = (float)(ow0 + p - 1 + k % 3) + offx;
        float y0f = floorf(py), x0f = floorf(px);
        int y0 = (int)y0f, x0 = (int)x0f;
        int y1 = y0 + 1,  x1 = x0 + 1;
        float wy1 = py - y0f, wy0 = 1.0f - wy1;
        float wx1 = px - x0f, wx0 = 1.0f - wx1;
        bool vy0 = (y0 >= 0 && y0 < Hn), vy1 = (y1 >= 0 && y1 < Hn);
        bool vx0 = (x0 >= 0 && x0 < Wn), vx1 = (x1 >= 0 && x1 < Wn);
        int cy0 = min(max(y0, 0), Hn - 1), cy1 = min(max(y1, 0), Hn - 1);
        int cx0 = min(max(x0, 0), Wn - 1), cx1 = min(max(x1, 0), Wn - 1);
        mw4[i] = make_float4(
            wy0 * wx0 * m * ((vy0 && vx0) ? 1.0f : 0.0f),
            wy0 * wx1 * m * ((vy0 && vx1) ? 1.0f : 0.0f),
            wy1 * wx0 * m * ((vy1 && vx0) ? 1.0f : 0.0f),
            wy1 * wx1 * m * ((vy1 && vx1) ? 1.0f : 0.0f));
        mo4[i] = make_int4(cy0 * Wn + cx0, cy0 * Wn + cx1,
                           cy1 * Wn + cx0, cy1 * Wn + cx1);
    }
    __syncthreads();

    const float* xtb = g_xt + (size_t)b * HWn * Cn;
    size_t arow0 = ((size_t)b * HWn + oh * Wn + ow0) * KP;

    for (int i = wid; i < 32 * KKn; i += 8) {
        int p = i / KKn;
        int k = i % KKn;
        float4 w = mw4[i];
        int4   o = mo4[i];
        const float* c00 = xtb + (size_t)o.x * Cn;
        const float* c01 = xtb + (size_t)o.y * Cn;
        const float* c10 = xtb + (size_t)o.z * Cn;
        const float* c11 = xtb + (size_t)o.w * Cn;
        __half2* dst = (__half2*)(g_A2 + arow0 + (size_t)p * KP) + k * Cn;
#pragma unroll
        for (int it = 0; it < 4; it++) {
            int c = it * 32 + lane;
            float v = w.x * c00[c] + w.y * c01[c]
                    + w.z * c10[c] + w.w * c11[c];
            __half hi = __float2half_rn(v);
            __half lo = __float2half_rn(v - __half2float(hi));
            dst[c] = __halves2half2(hi, lo);
        }
    }
}

// ---------------------------------------------------------------------------
// main GEMM: fp16 HMMA, CTA 128x128, BK=64, 3-stage (unchanged, verified R13)
// ---------------------------------------------------------------------------
static constexpr int PITCH  = 144;
static constexpr int ABYTES = BM * PITCH;         // 18432
static constexpr int BUFB   = 2 * ABYTES;         // 36864
static constexpr int GEMM_SMEM = 3 * BUFB;        // 110592

__global__ void __launch_bounds__(256, 2) gemm_kernel(
    const float* __restrict__ bias, float* __restrict__ out)
{
    extern __shared__ __align__(16) char sm[];
    uint32_t sb = smem_u32(sm);
    int tid  = threadIdx.x;
    int wid  = tid >> 5;
    int lane = tid & 31;
    int wm = wid & 3;
    int wn = wid >> 2;

    int row0 = blockIdx.y * BM;
    int col0 = blockIdx.x * BN;

    auto load_stage = [&](int s) {
        int kc = s * BK;
        uint32_t dst = sb + (s % 3) * BUFB;
#pragma unroll
        for (int i = 0; i < 4; i++) {
            int ch = tid + i * 256;
            int r = ch >> 3, u = ch & 7;
            cp_async16(dst + r * PITCH + u * 16,
                       g_A2 + (size_t)(row0 + r) * KP + kc + u * 8);
        }
        uint32_t dstb = dst + ABYTES;
#pragma unroll
        for (int i = 0; i < 4; i++) {
            int ch = tid + i * 256;
            int r = ch >> 3, u = ch & 7;
            cp_async16(dstb + r * PITCH + u * 16,
                       g_B2 + (size_t)(col0 + r) * KP + kc + u * 8);
        }
        CP_COMMIT();
    };

    float acc[2][8][4];
#pragma unroll
    for (int mt = 0; mt < 2; mt++)
#pragma unroll
        for (int nt = 0; nt < 8; nt++)
#pragma unroll
            for (int e = 0; e < 4; e++) acc[mt][nt][e] = 0.0f;

    load_stage(0);
    load_stage(1);

    int lrow = lane & 15;
    int lcol = (lane >> 4) * 8;

    for (int s = 0; s < NST; s++) {
        CP_WAIT1();
        __syncthreads();
        if (s + 2 < NST) load_stage(s + 2);

        uint32_t bufA = sb + (s % 3) * BUFB;
        uint32_t bufB = bufA + ABYTES;

#pragma unroll
        for (int kk = 0; kk < 4; kk++) {
            int colb = (kk * 16 + lcol) * 2;
            uint32_t a[2][4];
#pragma unroll
            for (int mt = 0; mt < 2; mt++) {
                int row = wm * 32 + mt * 16 + lrow;
                ldmx4(a[mt][0], a[mt][1], a[mt][2], a[mt][3],
                      bufA + row * PITCH + colb);
            }
#pragma unroll
            for (int ntp = 0; ntp < 4; ntp++) {
                int row = wn * 64 + ntp * 16 + lrow;
                uint32_t b0, b1, b2, b3;
                ldmx4(b0, b1, b2, b3, bufB + row * PITCH + colb);
#pragma unroll
                for (int mt = 0; mt < 2; mt++) {
                    mma_fp16(acc[mt][2 * ntp],     a[mt], b0, b2);
                    mma_fp16(acc[mt][2 * ntp + 1], a[mt], b1, b3);
                }
            }
        }
    }

    int quad = lane >> 2;
    int tq   = lane & 3;
#pragma unroll
    for (int mt = 0; mt < 2; mt++) {
        int m = row0 + wm * 32 + mt * 16 + quad;
        int b   = m / HWn;
        int pix = m % HWn;
        float* ob = out + (size_t)b * On * HWn;
#pragma unroll
        for (int nt = 0; nt < 8; nt++) {
            int o = col0 + wn * 64 + nt * 8 + tq * 2;
            float b0v = __ldg(bias + o);
            float b1v = __ldg(bias + o + 1);
            float* p0 = ob + (size_t)o * HWn + pix;
            float* p1 = ob + (size_t)(o + 1) * HWn + pix;
            p0[0] = acc[mt][nt][0] + b0v;
            p1[0] = acc[mt][nt][1] + b1v;
            p0[8] = acc[mt][nt][2] + b0v;
            p1[8] = acc[mt][nt][3] + b1v;
        }
    }
}

// ---------------------------------------------------------------------------
// Launch
// ---------------------------------------------------------------------------
extern "C" void kernel_launch(void* const* d_in, const int* in_sizes, int n_in,
                              void* d_out, int out_size)
{
    const float* x        = (const float*)d_in[0];
    const float* offset_w = (const float*)d_in[1];
    const float* offset_b = (const float*)d_in[2];
    const float* mask_w   = (const float*)d_in[3];
    const float* mask_b   = (const float*)d_in[4];
    const float* weight   = (const float*)d_in[5];
    const float* bias     = (const float*)d_in[6];
    float* out = (float*)d_out;

    cudaFuncSetAttribute(gemm_kernel,
                         cudaFuncAttributeMaxDynamicSharedMemorySize, GEMM_SMEM);
    cudaFuncSetAttribute(offmask_gemm,
                         cudaFuncAttributeMaxDynamicSharedMemorySize, OM_SMEM);

    prep_w<<<(On * CKn + 255) / 256, 256>>>(weight);
    prep_wo<<<(32 * CKn + 255) / 256, 256>>>(offset_w, mask_w);
    transpose_x<<<dim3(HWn / 32, Cn / 32, Bn), 256>>>(x);
    offmask_gemm<<<MTOT / 128, 256, OM_SMEM>>>(offset_b, mask_b);
    gather_kernel<<<Bn * Hn * 3, 256>>>();
    dim3 grid(On / BN, MTOT / BM);
    gemm_kernel<<<grid, 256, GEMM_SMEM>>>(bias, out);
}